// round 3
// baseline (speedup 1.0000x reference)
#include <cuda_runtime.h>
#include <math.h>

#define N_    64
#define C_    512
#define HW_   1024
#define K_    64
#define ALPHA_ 50.0f
#define EPS_  1e-12f

typedef unsigned long long ull;

// static scratch (allowed)
__device__ __align__(16) ull   g_Wd[C_ * K_];        // dup-packed col-normalized W  [c][k] -> (v,v)
__device__ __align__(16) float g_a [(size_t)N_ * K_ * HW_];   // soft assign [n][k][hw]
__device__ float g_ssq[N_ * K_ * 2];                 // vlad row ssq partials [n][k][chalf]

__device__ __forceinline__ ull ffma2(ull a, ull b, ull c) {
    ull r;
    asm("fma.rn.f32x2 %0, %1, %2, %3;" : "=l"(r) : "l"(a), "l"(b), "l"(c));
    return r;
}
__device__ __forceinline__ ull dup2(float v) {
    unsigned u = __float_as_uint(v);
    return ((ull)u << 32) | (ull)u;
}
__device__ __forceinline__ float2 u2f(ull v) {
    float2 f;
    f.x = __uint_as_float((unsigned)v);
    f.y = __uint_as_float((unsigned)(v >> 32));
    return f;
}

// ---------------------------------------------------------------------------
// K0: column-normalize W, store duplicated-pair packed g_Wd[c][k] = (wn, wn)
// ---------------------------------------------------------------------------
__global__ void k0_kernel(const float* __restrict__ w) {
    int k = blockIdx.x, tid = threadIdx.x;
    __shared__ float red[256];
    float ss = 0.f;
    for (int c = tid; c < C_; c += 256) { float v = w[c * K_ + k]; ss += v * v; }
    red[tid] = ss; __syncthreads();
    for (int s = 128; s > 0; s >>= 1) { if (tid < s) red[tid] += red[tid + s]; __syncthreads(); }
    float inv = 1.f / fmaxf(sqrtf(red[0]), EPS_);
    for (int c = tid; c < C_; c += 256) g_Wd[c * K_ + k] = dup2(w[c * K_ + k] * inv);
}

// ---------------------------------------------------------------------------
// K1: per (n, 256-hw tile): inv-norm prepass, feature write, GEMM1 (64k x 256j,
//     FFMA2 8k x 8j per thread), sa_logits out, softmax -> g_a
// smem floats: ls[64][264]=16896 (aliases xs[32][260] @0 and wd[32][66]ull @8320)
//              inv @16896 (256), bias @17152 (64) -> 17216 floats = 68864 B
// ---------------------------------------------------------------------------
#define S1_WD   8320
#define S1_INV  16896
#define S1_BIAS 17152
#define S1_TOT  17216

__global__ void __launch_bounds__(256, 2)
k1_kernel(const float* __restrict__ x, const float* __restrict__ bias,
          float* __restrict__ feat, float* __restrict__ sa) {
    extern __shared__ float sm[];
    float* xs  = sm;
    ull*   wd  = (ull*)(sm + S1_WD);
    float* inv = sm + S1_INV;
    float* bs  = sm + S1_BIAS;
    float* ls  = sm;

    int tid = threadIdx.x;
    int n   = blockIdx.x >> 2;
    int hw0 = (blockIdx.x & 3) << 8;
    int jg  = tid >> 3, kg = tid & 7;
    int j0  = jg * 8,  k0 = kg * 8;

    if (tid < K_) bs[tid] = bias[tid];

    // --- prepass: per-hw-column inverse L2 norm over C (j = tid) ---
    {
        const float* xp = x + (size_t)n * C_ * HW_ + hw0 + tid;
        float s0 = 0.f, s1 = 0.f, s2 = 0.f, s3 = 0.f;
        #pragma unroll 4
        for (int c = 0; c < C_; c += 4) {
            float v0 = xp[(size_t)(c    ) * HW_];
            float v1 = xp[(size_t)(c + 1) * HW_];
            float v2 = xp[(size_t)(c + 2) * HW_];
            float v3 = xp[(size_t)(c + 3) * HW_];
            s0 += v0 * v0; s1 += v1 * v1; s2 += v2 * v2; s3 += v3 * v3;
        }
        inv[tid] = 1.f / fmaxf(sqrtf((s0 + s1) + (s2 + s3)), EPS_);
    }
    __syncthreads();

    ull acc[8][4];
    #pragma unroll
    for (int i = 0; i < 8; i++)
        #pragma unroll
        for (int p = 0; p < 4; p++) acc[i][p] = 0ull;

    for (int cc = 0; cc < C_; cc += 32) {
        __syncthreads();
        // stage x chunk [32c][256j] (pad 260) and dup-W chunk [32c][64k ull] (pad 66 ull)
        {
            const float4* src = (const float4*)(x + ((size_t)(n * C_ + cc)) * HW_ + hw0);
            #pragma unroll
            for (int it = 0; it < 8; it++) {
                int idx = tid + it * 256;
                int c = idx >> 6, q = idx & 63;
                float4 v = src[(size_t)c * 256 + q];
                *(float4*)(xs + c * 260 + 4 * q) = v;
            }
            // FIX (R2 bug): full coverage — 32 c-rows x 64 ulls = 1024 float4
            const float4* wsrc = (const float4*)(g_Wd + cc * K_);
            #pragma unroll
            for (int it = 0; it < 4; it++) {
                int idx = tid + it * 256;
                int c = idx >> 5, q = idx & 31;
                float4 v = wsrc[c * 32 + q];
                *(float4*)((float*)(wd + c * 66) + 4 * q) = v;
            }
        }
        __syncthreads();
        // feature write: feat[n][hw0+j][cc + c4 .. +3] = xs[c][j] * inv[j]
        {
            float* fdst = feat + ((size_t)(n * HW_ + hw0)) * C_ + cc;
            #pragma unroll
            for (int it = 0; it < 8; it++) {
                int idx = tid + it * 256;
                int j = idx >> 3, c4 = (idx & 7) * 4;
                float iv = inv[j];
                float4 v;
                v.x = xs[(c4 + 0) * 260 + j] * iv;
                v.y = xs[(c4 + 1) * 260 + j] * iv;
                v.z = xs[(c4 + 2) * 260 + j] * iv;
                v.w = xs[(c4 + 3) * 260 + j] * iv;
                *(float4*)(fdst + (size_t)j * C_ + c4) = v;
            }
        }
        // GEMM chunk: 32 c-steps, 8k x 4 j-pairs FFMA2 per thread
        #pragma unroll 4
        for (int c = 0; c < 32; c++) {
            const ull* xp = (const ull*)(xs + c * 260 + j0);
            ulonglong2 x01 = *(const ulonglong2*)(xp);
            ulonglong2 x23 = *(const ulonglong2*)(xp + 2);
            const ull* wp = wd + c * 66 + k0;
            ulonglong2 w01 = *(const ulonglong2*)(wp);
            ulonglong2 w23 = *(const ulonglong2*)(wp + 2);
            ulonglong2 w45 = *(const ulonglong2*)(wp + 4);
            ulonglong2 w67 = *(const ulonglong2*)(wp + 6);
            ull wv[8] = {w01.x, w01.y, w23.x, w23.y, w45.x, w45.y, w67.x, w67.y};
            ull xv[4] = {x01.x, x01.y, x23.x, x23.y};
            #pragma unroll
            for (int i = 0; i < 8; i++)
                #pragma unroll
                for (int p = 0; p < 4; p++)
                    acc[i][p] = ffma2(wv[i], xv[p], acc[i][p]);
        }
    }
    __syncthreads();

    // epilogue: ls[k][j] = acc * inv[j]
    {
        float iv[8];
        #pragma unroll
        for (int p = 0; p < 8; p++) iv[p] = inv[j0 + p];
        #pragma unroll
        for (int i = 0; i < 8; i++)
            #pragma unroll
            for (int p = 0; p < 4; p++) {
                float2 v = u2f(acc[i][p]);
                v.x *= iv[2 * p]; v.y *= iv[2 * p + 1];
                *(float2*)(ls + (k0 + i) * 264 + j0 + 2 * p) = v;
            }
    }
    __syncthreads();

    // raw sa_logits out (coalesced)
    {
        float* sp = sa + (size_t)n * K_ * HW_ + hw0;
        #pragma unroll
        for (int it = 0; it < 16; it++) {
            int idx = tid + it * 256;
            int k = idx >> 6, q = idx & 63;
            *(float4*)(sp + (size_t)k * HW_ + 4 * q) = *(const float4*)(ls + k * 264 + 4 * q);
        }
    }
    __syncthreads();

    // softmax over k, column j = tid, (logit + bias) * ALPHA
    {
        int j = tid;
        float m = -1e30f;
        #pragma unroll 8
        for (int k = 0; k < K_; k++) {
            float v = (ls[k * 264 + j] + bs[k]) * ALPHA_;
            m = fmaxf(m, v);
        }
        float s = 0.f;
        #pragma unroll 8
        for (int k = 0; k < K_; k++) {
            float e = __expf((ls[k * 264 + j] + bs[k]) * ALPHA_ - m);
            ls[k * 264 + j] = e; s += e;
        }
        float is = 1.f / s;
        #pragma unroll 8
        for (int k = 0; k < K_; k++) ls[k * 264 + j] *= is;
    }
    __syncthreads();

    {
        float* ap = g_a + (size_t)n * K_ * HW_ + hw0;
        #pragma unroll
        for (int it = 0; it < 16; it++) {
            int idx = tid + it * 256;
            int k = idx >> 6, q = idx & 63;
            *(float4*)(ap + (size_t)k * HW_ + 4 * q) = *(const float4*)(ls + k * 264 + 4 * q);
        }
    }
}

// ---------------------------------------------------------------------------
// K2: per (n, 256-c half): vlad_raw[64k][256c] = a @ feature - asum*W^T,
//     FFMA2 8k x 8c per thread; writes raw vlad + per-row ssq partials.
// smem floats: fs[32][264]=8448, ad(ull)[32][66] @8448 (4224 f),
//              asum @12672 (64), red @12736 (2112) -> 14848 floats = 59392 B
// ---------------------------------------------------------------------------
#define S2_AD   8448
#define S2_ASUM 12672
#define S2_RED  12736
#define S2_TOT  14848

__global__ void __launch_bounds__(256)
k2_kernel(const float* __restrict__ w, const float* __restrict__ feat,
          float* __restrict__ vlad) {
    extern __shared__ float sm[];
    float* fs    = sm;
    ull*   ad    = (ull*)(sm + S2_AD);
    float* asums = sm + S2_ASUM;
    float* red   = sm + S2_RED;

    int tid  = threadIdx.x;
    int n    = blockIdx.x >> 1;
    int ch   = blockIdx.x & 1;
    int c0b  = ch << 8;
    int kg   = tid & 7, cg = tid >> 3;
    int k0   = kg * 8,  c0 = cg * 8;

    // asum prepass (deterministic 4-way split per k)
    {
        int k = tid >> 2, q = tid & 3;
        const float4* ap = (const float4*)(g_a + (size_t)n * K_ * HW_ + (size_t)k * HW_ + q * 256);
        float s = 0.f;
        #pragma unroll 8
        for (int i = 0; i < 64; i++) { float4 v = ap[i]; s += (v.x + v.y) + (v.z + v.w); }
        red[k * 4 + q] = s;
    }
    __syncthreads();
    if (tid < K_)
        asums[tid] = (red[tid * 4] + red[tid * 4 + 1]) + (red[tid * 4 + 2] + red[tid * 4 + 3]);

    ull acc[8][4];
    #pragma unroll
    for (int i = 0; i < 8; i++)
        #pragma unroll
        for (int p = 0; p < 4; p++) acc[i][p] = 0ull;

    for (int hw = 0; hw < HW_; hw += 32) {
        __syncthreads();
        // stage feature chunk [32j][256c]
        {
            const float4* src = (const float4*)(feat + ((size_t)(n * HW_ + hw)) * C_ + c0b);
            #pragma unroll
            for (int it = 0; it < 8; it++) {
                int idx = tid + it * 256;
                int j = idx >> 6, q = idx & 63;
                float4 v = src[(size_t)j * 128 + q];
                *(float4*)(fs + j * 264 + 4 * q) = v;
            }
        }
        // stage a chunk duplicated: ad[j][k] = (a,a)
        {
            const float* abase = g_a + (size_t)n * K_ * HW_ + hw;
            #pragma unroll
            for (int it = 0; it < 2; it++) {
                int idx = tid + it * 256;
                int k = idx >> 3, jq = idx & 7;
                float4 v = *(const float4*)(abase + (size_t)k * HW_ + 4 * jq);
                ad[(4 * jq + 0) * 66 + k] = dup2(v.x);
                ad[(4 * jq + 1) * 66 + k] = dup2(v.y);
                ad[(4 * jq + 2) * 66 + k] = dup2(v.z);
                ad[(4 * jq + 3) * 66 + k] = dup2(v.w);
            }
        }
        __syncthreads();
        #pragma unroll 4
        for (int j = 0; j < 32; j++) {
            const ull* ap = ad + j * 66 + k0;
            ulonglong2 a01 = *(const ulonglong2*)(ap);
            ulonglong2 a23 = *(const ulonglong2*)(ap + 2);
            ulonglong2 a45 = *(const ulonglong2*)(ap + 4);
            ulonglong2 a67 = *(const ulonglong2*)(ap + 6);
            const ull* fp = (const ull*)(fs + j * 264 + c0);
            ulonglong2 f01 = *(const ulonglong2*)(fp);
            ulonglong2 f23 = *(const ulonglong2*)(fp + 2);
            ull av[8] = {a01.x, a01.y, a23.x, a23.y, a45.x, a45.y, a67.x, a67.y};
            ull fv[4] = {f01.x, f01.y, f23.x, f23.y};
            #pragma unroll
            for (int i = 0; i < 8; i++)
                #pragma unroll
                for (int p = 0; p < 4; p++)
                    acc[i][p] = ffma2(av[i], fv[p], acc[i][p]);
        }
    }
    __syncthreads();

    // epilogue: centroid subtract (raw W), write raw vlad, ssq partials
    #pragma unroll
    for (int i = 0; i < 8; i++) {
        int k = k0 + i;
        float as_ = asums[k];
        float out[8]; float ssq = 0.f;
        #pragma unroll
        for (int p = 0; p < 4; p++) {
            float2 v = u2f(acc[i][p]);
            int c = c0b + c0 + 2 * p;
            float t0 = v.x - as_ * w[(size_t)c * K_ + k];
            float t1 = v.y - as_ * w[(size_t)(c + 1) * K_ + k];
            out[2 * p] = t0; out[2 * p + 1] = t1;
            ssq += t0 * t0 + t1 * t1;
        }
        float4 o0 = {out[0], out[1], out[2], out[3]};
        float4 o1 = {out[4], out[5], out[6], out[7]};
        float* vp = vlad + (size_t)n * K_ * C_ + (size_t)k * C_ + c0b + c0;
        *(float4*)(vp)     = o0;
        *(float4*)(vp + 4) = o1;
        red[k * 33 + cg] = ssq;
    }
    __syncthreads();
    if (tid < K_) {
        float s = 0.f;
        #pragma unroll
        for (int c = 0; c < 32; c++) s += red[tid * 33 + c];
        g_ssq[n * 128 + tid * 2 + ch] = s;
    }
}

// ---------------------------------------------------------------------------
// K3: in-place row L2 norm of vlad from ssq partials
// ---------------------------------------------------------------------------
__global__ void k3_kernel(float* __restrict__ vlad) {
    int row = blockIdx.x;                          // 4096 = n*64 + k
    float ssq = g_ssq[row * 2] + g_ssq[row * 2 + 1];
    float iv  = 1.f / fmaxf(sqrtf(ssq), EPS_);
    float4* vp = (float4*)(vlad + (size_t)row * C_);
    float4 v = vp[threadIdx.x];
    v.x *= iv; v.y *= iv; v.z *= iv; v.w *= iv;
    vp[threadIdx.x] = v;
}

// ---------------------------------------------------------------------------
extern "C" void kernel_launch(void* const* d_in, const int* in_sizes, int n_in,
                              void* d_out, int out_size) {
    const float* x    = (const float*)d_in[0];   // [64,512,32,32]
    const float* w    = (const float*)d_in[1];   // [512,64]
    const float* bias = (const float*)d_in[2];   // [64]
    float* out  = (float*)d_out;
    float* vlad = out;                                    // [64, 64*512]
    float* sa   = out + (size_t)N_ * K_ * C_;             // [64, 64, 1024]
    float* feat = sa  + (size_t)N_ * K_ * HW_;            // [64, 1024, 512]

    cudaFuncSetAttribute(k1_kernel, cudaFuncAttributeMaxDynamicSharedMemorySize,
                         S1_TOT * (int)sizeof(float));
    cudaFuncSetAttribute(k2_kernel, cudaFuncAttributeMaxDynamicSharedMemorySize,
                         S2_TOT * (int)sizeof(float));

    k0_kernel<<<K_, 256>>>(w);
    k1_kernel<<<N_ * 4, 256, S1_TOT * sizeof(float)>>>(x, bias, feat, sa);
    k2_kernel<<<N_ * 2, 256, S2_TOT * sizeof(float)>>>(w, feat, vlad);
    k3_kernel<<<N_ * K_, 128>>>(vlad);
}

// round 7
// speedup vs baseline: 3.1178x; 3.1178x over previous
#include <cuda_runtime.h>
#include <cuda_bf16.h>
#include <math.h>
#include <stdint.h>

#define N_    64
#define C_    512
#define HW_   1024
#define K_    64
#define ALPHA_ 50.0f
#define EPS_  1e-12f

typedef unsigned long long ull;

// static scratch
__device__ __align__(16) float g_WnT[K_ * C_];              // col-normalized W^T [k][c]
__device__ __align__(16) float g_inv[N_ * HW_];             // 1/||x[n,:,hw]||
__device__ __align__(16) float g_a[(size_t)N_ * K_ * HW_];  // soft assign [n][k][hw]
__device__ __align__(16) float g_asum[N_ * K_];
__device__ __align__(16) float g_ssq[N_ * K_ * 4];

// ---------------------------------------------------------------------------
__device__ __forceinline__ void mma16816(float* c, uint32_t a0, uint32_t a1,
                                         uint32_t a2, uint32_t a3,
                                         uint32_t b0, uint32_t b1) {
    asm volatile(
        "mma.sync.aligned.m16n8k16.row.col.f32.bf16.bf16.f32 "
        "{%0,%1,%2,%3}, {%4,%5,%6,%7}, {%8,%9}, {%0,%1,%2,%3};"
        : "+f"(c[0]), "+f"(c[1]), "+f"(c[2]), "+f"(c[3])
        : "r"(a0), "r"(a1), "r"(a2), "r"(a3), "r"(b0), "r"(b1));
}

// split f32 -> (hi, lo) bf16 pairs; byte_off into [row][72-bf16] padded arrays
__device__ __forceinline__ void store_split(char* hi, char* lo, uint32_t byte_off, float4 v) {
    float f[4] = {v.x, v.y, v.z, v.w};
    ull ph = 0, pl = 0;
    #pragma unroll
    for (int i = 0; i < 4; i++) {
        __nv_bfloat16 h = __float2bfloat16_rn(f[i]);
        __nv_bfloat16 l = __float2bfloat16_rn(f[i] - __bfloat162float(h));
        ph |= (ull)(unsigned short)__bfloat16_as_ushort(h) << (16 * i);
        pl |= (ull)(unsigned short)__bfloat16_as_ushort(l) << (16 * i);
    }
    *(ull*)(hi + byte_off) = ph;
    *(ull*)(lo + byte_off) = pl;
}

// ---------------------------------------------------------------------------
// k0: Wn^T[k][c] = W[c][k]/||W[:,k]||
// ---------------------------------------------------------------------------
__global__ void k0_kernel(const float* __restrict__ w) {
    int k = blockIdx.x, tid = threadIdx.x;
    __shared__ float red[256];
    float ss = 0.f;
    for (int c = tid; c < C_; c += 256) { float v = w[c * K_ + k]; ss += v * v; }
    red[tid] = ss; __syncthreads();
    for (int s = 128; s > 0; s >>= 1) { if (tid < s) red[tid] += red[tid + s]; __syncthreads(); }
    float inv = 1.f / fmaxf(sqrtf(red[0]), EPS_);
    for (int c = tid; c < C_; c += 256) g_WnT[k * C_ + c] = w[c * K_ + k] * inv;
}

// ---------------------------------------------------------------------------
// kInv: g_inv[n][hw]
// ---------------------------------------------------------------------------
__global__ void kInv(const float* __restrict__ x) {
    int n = blockIdx.x >> 2;
    int h = ((blockIdx.x & 3) << 8) + threadIdx.x;
    const float* xp = x + (size_t)n * C_ * HW_ + h;
    float s0 = 0.f, s1 = 0.f, s2 = 0.f, s3 = 0.f;
    #pragma unroll 4
    for (int c = 0; c < C_; c += 4) {
        float v0 = xp[(size_t)(c    ) * HW_];
        float v1 = xp[(size_t)(c + 1) * HW_];
        float v2 = xp[(size_t)(c + 2) * HW_];
        float v3 = xp[(size_t)(c + 3) * HW_];
        s0 += v0 * v0; s1 += v1 * v1; s2 += v2 * v2; s3 += v3 * v3;
    }
    g_inv[n * HW_ + h] = 1.f / fmaxf(sqrtf((s0 + s1) + (s2 + s3)), EPS_);
}

// ---------------------------------------------------------------------------
// kT: feature[n][hw][c] = x[n][c][hw] * inv[n][hw]
// ---------------------------------------------------------------------------
__global__ void __launch_bounds__(256) kT(const float* __restrict__ x, float* __restrict__ feat) {
    __shared__ float xs[128 * 33];
    __shared__ float iv[32];
    int b = blockIdx.x;
    int n = b >> 7, r = b & 127;
    int hw0 = (r >> 2) * 32, c0 = (r & 3) * 128;
    int tid = threadIdx.x;

    if (tid < 32) iv[tid] = g_inv[n * HW_ + hw0 + tid];
    #pragma unroll
    for (int it = 0; it < 4; it++) {
        int idx = tid + it * 256;
        int c = idx >> 3, q = idx & 7;
        float4 v = *(const float4*)(x + ((size_t)n * C_ + c0 + c) * HW_ + hw0 + 4 * q);
        xs[c * 33 + 4 * q    ] = v.x;
        xs[c * 33 + 4 * q + 1] = v.y;
        xs[c * 33 + 4 * q + 2] = v.z;
        xs[c * 33 + 4 * q + 3] = v.w;
    }
    __syncthreads();
    #pragma unroll
    for (int it = 0; it < 4; it++) {
        int idx = tid + it * 256;
        int hw = idx >> 5, cq = idx & 31;
        float s = iv[hw];
        float4 v;
        v.x = xs[(4 * cq    ) * 33 + hw] * s;
        v.y = xs[(4 * cq + 1) * 33 + hw] * s;
        v.z = xs[(4 * cq + 2) * 33 + hw] * s;
        v.w = xs[(4 * cq + 3) * 33 + hw] * s;
        *(float4*)(feat + ((size_t)n * HW_ + hw0 + hw) * C_ + c0 + 4 * cq) = v;
    }
}

// ---------------------------------------------------------------------------
// kG1: D[128hw][64k] = feat @ WnT^T (contraction c), split-bf16 3-pass mma.sync.
// Epilogue: sa_logits + softmax -> g_a.
// smem bytes: staging Ahi|Alo (128*72*2 each) Bhi|Blo (64*72*2 each) = 55296,
//             ls f32[128][67] aliases staging, bias @55296 (256) -> 55552
// ---------------------------------------------------------------------------
#define G1_ALO  18432
#define G1_BHI  36864
#define G1_BLO  46080
#define G1_BIAS 55296
#define G1_SMEM 55552

__global__ void __launch_bounds__(256, 2)
kG1(const float* __restrict__ feat, const float* __restrict__ bias, float* __restrict__ sa) {
    extern __shared__ char sm[];
    char* Ahi = sm;
    char* Alo = sm + G1_ALO;
    char* Bhi = sm + G1_BHI;
    char* Blo = sm + G1_BLO;
    float* ls = (float*)sm;                       // alias (used after GEMM)
    float* bsm = (float*)(sm + G1_BIAS);

    int tid = threadIdx.x, wid = tid >> 5, lane = tid & 31;
    int g = lane >> 2, t = lane & 3;
    int row0 = wid * 16;
    int n = blockIdx.x >> 3, hw0 = (blockIdx.x & 7) << 7;

    if (tid < K_) bsm[tid] = bias[tid];

    float acc[8][4];
    #pragma unroll
    for (int nb = 0; nb < 8; nb++)
        #pragma unroll
        for (int i = 0; i < 4; i++) acc[nb][i] = 0.f;

    for (int cc = 0; cc < C_; cc += 64) {
        __syncthreads();
        // stage A [128 hw][64 c] split
        #pragma unroll
        for (int it = 0; it < 8; it++) {
            int idx = tid + it * 256;
            int row = idx >> 4, q = idx & 15;
            float4 v = *(const float4*)(feat + ((size_t)(n * HW_ + hw0 + row)) * C_ + cc + 4 * q);
            store_split(Ahi, Alo, (uint32_t)(row * 72 + 4 * q) * 2, v);
        }
        // stage B [64 k][64 c] split
        #pragma unroll
        for (int it = 0; it < 4; it++) {
            int idx = tid + it * 256;
            int row = idx >> 4, q = idx & 15;
            float4 v = *(const float4*)(g_WnT + row * C_ + cc + 4 * q);
            store_split(Bhi, Blo, (uint32_t)(row * 72 + 4 * q) * 2, v);
        }
        __syncthreads();
        #pragma unroll
        for (int pass = 0; pass < 3; pass++) {
            const char* Ab = (pass == 2) ? Alo : Ahi;
            const char* Bb = (pass == 1) ? Blo : Bhi;
            #pragma unroll
            for (int kk = 0; kk < 64; kk += 16) {
                uint32_t a0 = *(const uint32_t*)(Ab + ((row0 + g    ) * 72 + kk +     2 * t) * 2);
                uint32_t a1 = *(const uint32_t*)(Ab + ((row0 + g + 8) * 72 + kk +     2 * t) * 2);
                uint32_t a2 = *(const uint32_t*)(Ab + ((row0 + g    ) * 72 + kk + 8 + 2 * t) * 2);
                uint32_t a3 = *(const uint32_t*)(Ab + ((row0 + g + 8) * 72 + kk + 8 + 2 * t) * 2);
                #pragma unroll
                for (int nb = 0; nb < 8; nb++) {
                    uint32_t b0 = *(const uint32_t*)(Bb + ((nb * 8 + g) * 72 + kk +     2 * t) * 2);
                    uint32_t b1 = *(const uint32_t*)(Bb + ((nb * 8 + g) * 72 + kk + 8 + 2 * t) * 2);
                    mma16816(acc[nb], a0, a1, a2, a3, b0, b1);
                }
            }
        }
    }
    __syncthreads();
    // dump frags to ls[row][67]
    #pragma unroll
    for (int nb = 0; nb < 8; nb++) {
        int col = nb * 8 + 2 * t;
        ls[(row0 + g    ) * 67 + col    ] = acc[nb][0];
        ls[(row0 + g    ) * 67 + col + 1] = acc[nb][1];
        ls[(row0 + g + 8) * 67 + col    ] = acc[nb][2];
        ls[(row0 + g + 8) * 67 + col + 1] = acc[nb][3];
    }
    __syncthreads();
    if (tid < 128) {
        int hw = hw0 + tid;
        float f[64];
        float m = -1e30f;
        float* sp = sa + (size_t)n * K_ * HW_ + hw;
        #pragma unroll
        for (int k = 0; k < K_; k++) {
            float raw = ls[tid * 67 + k];
            sp[(size_t)k * HW_] = raw;
            float v = (raw + bsm[k]) * ALPHA_;
            f[k] = v;
            m = fmaxf(m, v);
        }
        float s = 0.f;
        #pragma unroll
        for (int k = 0; k < K_; k++) { float e = __expf(f[k] - m); f[k] = e; s += e; }
        float is = 1.f / s;
        float* ap = g_a + (size_t)n * K_ * HW_ + hw;
        #pragma unroll
        for (int k = 0; k < K_; k++) ap[(size_t)k * HW_] = f[k] * is;
    }
}

// ---------------------------------------------------------------------------
// kAsum: g_asum[n][k] = sum_h a[n][k][h]
// ---------------------------------------------------------------------------
__global__ void kAsum() {
    __shared__ float red[256];
    int n = blockIdx.x, tid = threadIdx.x;
    int k = tid >> 2, q = tid & 3;
    const float4* ap = (const float4*)(g_a + (size_t)n * K_ * HW_ + (size_t)k * HW_ + q * 256);
    float s = 0.f;
    #pragma unroll 8
    for (int i = 0; i < 64; i++) { float4 v = ap[i]; s += (v.x + v.y) + (v.z + v.w); }
    red[tid] = s;
    __syncthreads();
    if (tid < K_)
        g_asum[n * K_ + tid] = (red[tid * 4] + red[tid * 4 + 1]) + (red[tid * 4 + 2] + red[tid * 4 + 3]);
}

// ---------------------------------------------------------------------------
// kG2: D[128c][64k] = (x*inv) @ a^T (contraction h), split-bf16 3-pass.
// Epilogue: subtract asum*W, write raw vlad, ssq partials.
// smem: staging 55296 (ls aliases), asum @55296 (256), ivs[1024] @55552 (4096)
// ---------------------------------------------------------------------------
#define G2_ASUM 55296
#define G2_IVS  55552
#define G2_SMEM 59648

__global__ void __launch_bounds__(256, 2)
kG2(const float* __restrict__ x, const float* __restrict__ w, float* __restrict__ vlad) {
    extern __shared__ char sm[];
    char* Ahi = sm;
    char* Alo = sm + G1_ALO;
    char* Bhi = sm + G1_BHI;
    char* Blo = sm + G1_BLO;
    float* ls   = (float*)sm;
    float* asum = (float*)(sm + G2_ASUM);
    float* ivs  = (float*)(sm + G2_IVS);

    int tid = threadIdx.x, wid = tid >> 5, lane = tid & 31;
    int g = lane >> 2, t = lane & 3;
    int row0 = wid * 16;
    int n = blockIdx.x >> 2, ct = blockIdx.x & 3;
    int c0b = ct << 7;

    if (tid < K_) asum[tid] = g_asum[n * K_ + tid];
    *(float4*)(ivs + 4 * tid) = *(const float4*)(g_inv + n * HW_ + 4 * tid);

    float acc[8][4];
    #pragma unroll
    for (int nb = 0; nb < 8; nb++)
        #pragma unroll
        for (int i = 0; i < 4; i++) acc[nb][i] = 0.f;

    __syncthreads();
    for (int h0 = 0; h0 < HW_; h0 += 64) {
        __syncthreads();
        // stage A [128 c][64 h] = x * inv, split
        #pragma unroll
        for (int it = 0; it < 8; it++) {
            int idx = tid + it * 256;
            int row = idx >> 4, q = idx & 15;
            float4 v = *(const float4*)(x + ((size_t)n * C_ + c0b + row) * HW_ + h0 + 4 * q);
            float4 iv = *(const float4*)(ivs + h0 + 4 * q);
            v.x *= iv.x; v.y *= iv.y; v.z *= iv.z; v.w *= iv.w;
            store_split(Ahi, Alo, (uint32_t)(row * 72 + 4 * q) * 2, v);
        }
        // stage B [64 k][64 h] = a, split
        #pragma unroll
        for (int it = 0; it < 4; it++) {
            int idx = tid + it * 256;
            int row = idx >> 4, q = idx & 15;
            float4 v = *(const float4*)(g_a + (size_t)n * K_ * HW_ + (size_t)row * HW_ + h0 + 4 * q);
            store_split(Bhi, Blo, (uint32_t)(row * 72 + 4 * q) * 2, v);
        }
        __syncthreads();
        #pragma unroll
        for (int pass = 0; pass < 3; pass++) {
            const char* Ab = (pass == 2) ? Alo : Ahi;
            const char* Bb = (pass == 1) ? Blo : Bhi;
            #pragma unroll
            for (int kk = 0; kk < 64; kk += 16) {
                uint32_t a0 = *(const uint32_t*)(Ab + ((row0 + g    ) * 72 + kk +     2 * t) * 2);
                uint32_t a1 = *(const uint32_t*)(Ab + ((row0 + g + 8) * 72 + kk +     2 * t) * 2);
                uint32_t a2 = *(const uint32_t*)(Ab + ((row0 + g    ) * 72 + kk + 8 + 2 * t) * 2);
                uint32_t a3 = *(const uint32_t*)(Ab + ((row0 + g + 8) * 72 + kk + 8 + 2 * t) * 2);
                #pragma unroll
                for (int nb = 0; nb < 8; nb++) {
                    uint32_t b0 = *(const uint32_t*)(Bb + ((nb * 8 + g) * 72 + kk +     2 * t) * 2);
                    uint32_t b1 = *(const uint32_t*)(Bb + ((nb * 8 + g) * 72 + kk + 8 + 2 * t) * 2);
                    mma16816(acc[nb], a0, a1, a2, a3, b0, b1);
                }
            }
        }
    }
    __syncthreads();
    #pragma unroll
    for (int nb = 0; nb < 8; nb++) {
        int col = nb * 8 + 2 * t;
        ls[(row0 + g    ) * 67 + col    ] = acc[nb][0];
        ls[(row0 + g    ) * 67 + col + 1] = acc[nb][1];
        ls[(row0 + g + 8) * 67 + col    ] = acc[nb][2];
        ls[(row0 + g + 8) * 67 + col + 1] = acc[nb][3];
    }
    __syncthreads();
    if (tid < 128) {
        int c = c0b + tid;
        float f[64];
        #pragma unroll
        for (int i = 0; i < 16; i++) {
            float4 wv = *(const float4*)(w + (size_t)c * K_ + 4 * i);
            f[4 * i    ] = ls[tid * 67 + 4 * i    ] - asum[4 * i    ] * wv.x;
            f[4 * i + 1] = ls[tid * 67 + 4 * i + 1] - asum[4 * i + 1] * wv.y;
            f[4 * i + 2] = ls[tid * 67 + 4 * i + 2] - asum[4 * i + 2] * wv.z;
            f[4 * i + 3] = ls[tid * 67 + 4 * i + 3] - asum[4 * i + 3] * wv.w;
        }
        float* vp = vlad + (size_t)n * K_ * C_ + c;
        #pragma unroll
        for (int k = 0; k < K_; k++) {
            vp[(size_t)k * C_] = f[k];
            ls[tid * 67 + k] = f[k];
        }
    }
    __syncthreads();
    if (tid < K_) {
        float s = 0.f;
        #pragma unroll 4
        for (int c = 0; c < 128; c++) { float v = ls[c * 67 + tid]; s += v * v; }
        g_ssq[(n * K_ + tid) * 4 + ct] = s;
    }
}

// ---------------------------------------------------------------------------
// k3: row L2 norm of vlad
// ---------------------------------------------------------------------------
__global__ void k3_kernel(float* __restrict__ vlad) {
    int row = blockIdx.x;
    const float* sp = g_ssq + row * 4;
    float ssq = (sp[0] + sp[1]) + (sp[2] + sp[3]);
    float iv = 1.f / fmaxf(sqrtf(ssq), EPS_);
    float4* vp = (float4*)(vlad + (size_t)row * C_);
    float4 v = vp[threadIdx.x];
    v.x *= iv; v.y *= iv; v.z *= iv; v.w *= iv;
    vp[threadIdx.x] = v;
}

// ---------------------------------------------------------------------------
extern "C" void kernel_launch(void* const* d_in, const int* in_sizes, int n_in,
                              void* d_out, int out_size) {
    const float* x    = (const float*)d_in[0];   // [64,512,32,32]
    const float* w    = (const float*)d_in[1];   // [512,64]
    const float* bias = (const float*)d_in[2];   // [64]
    float* out  = (float*)d_out;
    float* vlad = out;                                    // [64, 64*512]
    float* sa   = out + (size_t)N_ * K_ * C_;             // [64, 64, 1024]
    float* feat = sa  + (size_t)N_ * K_ * HW_;            // [64, 1024, 512]

    cudaFuncSetAttribute(kG1, cudaFuncAttributeMaxDynamicSharedMemorySize, G1_SMEM);
    cudaFuncSetAttribute(kG2, cudaFuncAttributeMaxDynamicSharedMemorySize, G2_SMEM);

    k0_kernel<<<K_, 256>>>(w);
    kInv<<<N_ * 4, 256>>>(x);
    kT<<<N_ * 128, 256>>>(x, feat);
    kG1<<<N_ * 8, 256, G1_SMEM>>>(feat, bias, sa);
    kAsum<<<N_, 256>>>();
    kG2<<<N_ * 4, 256, G2_SMEM>>>(x, w, vlad);
    k3_kernel<<<N_ * K_, 128>>>(vlad);
}

// round 12
// speedup vs baseline: 3.2226x; 1.0336x over previous
#include <cuda_runtime.h>
#include <cuda_bf16.h>
#include <math.h>
#include <stdint.h>

#define N_    64
#define C_    512
#define HW_   1024
#define K_    64
#define ALPHA_ 50.0f
#define EPS_  1e-12f

typedef unsigned long long ull;

// single extern shared symbol for all kernels
extern __shared__ char smem_u[];

// static scratch
__device__ __align__(16) float g_WnT[K_ * C_];              // col-normalized W^T [k][c]
__device__ __align__(16) float g_inv[N_ * HW_];             // 1/||x[n,:,hw]||
__device__ __align__(16) float g_a[(size_t)N_ * K_ * HW_];  // soft assign [n][k][hw]
__device__ __align__(16) float g_asum[N_ * K_];
__device__ __align__(16) float g_ssq[N_ * K_ * 4];

// ---------------------------------------------------------------------------
__device__ __forceinline__ uint32_t s2u(const void* p) {
    uint32_t a;
    asm("{ .reg .u64 t; cvta.to.shared.u64 t, %1; cvt.u32.u64 %0, t; }" : "=r"(a) : "l"(p));
    return a;
}
__device__ __forceinline__ void mma16816(float* c, uint32_t a0, uint32_t a1,
                                         uint32_t a2, uint32_t a3,
                                         uint32_t b0, uint32_t b1) {
    asm volatile(
        "mma.sync.aligned.m16n8k16.row.col.f32.bf16.bf16.f32 "
        "{%0,%1,%2,%3}, {%4,%5,%6,%7}, {%8,%9}, {%0,%1,%2,%3};"
        : "+f"(c[0]), "+f"(c[1]), "+f"(c[2]), "+f"(c[3])
        : "r"(a0), "r"(a1), "r"(a2), "r"(a3), "r"(b0), "r"(b1));
}
__device__ __forceinline__ void ldsm_x4(uint32_t& r0, uint32_t& r1, uint32_t& r2,
                                        uint32_t& r3, uint32_t addr) {
    asm volatile("ldmatrix.sync.aligned.m8n8.x4.shared.b16 {%0,%1,%2,%3}, [%4];"
                 : "=r"(r0), "=r"(r1), "=r"(r2), "=r"(r3) : "r"(addr));
}

// split f32 -> (hi, lo) bf16 pairs; byte_off into [row][72-bf16] padded arrays
__device__ __forceinline__ void store_split(char* hi, char* lo, uint32_t byte_off, float4 v) {
    float f[4] = {v.x, v.y, v.z, v.w};
    ull ph = 0, pl = 0;
    #pragma unroll
    for (int i = 0; i < 4; i++) {
        __nv_bfloat16 h = __float2bfloat16_rn(f[i]);
        __nv_bfloat16 l = __float2bfloat16_rn(f[i] - __bfloat162float(h));
        ph |= (ull)(unsigned short)__bfloat16_as_ushort(h) << (16 * i);
        pl |= (ull)(unsigned short)__bfloat16_as_ushort(l) << (16 * i);
    }
    *(ull*)(hi + byte_off) = ph;
    *(ull*)(lo + byte_off) = pl;
}

// ---------------------------------------------------------------------------
// k0: Wn^T[k][c] = W[c][k]/||W[:,k]||
// ---------------------------------------------------------------------------
__global__ void k0_kernel(const float* __restrict__ w) {
    int k = blockIdx.x, tid = threadIdx.x;
    __shared__ float red[256];
    float ss = 0.f;
    for (int c = tid; c < C_; c += 256) { float v = w[c * K_ + k]; ss += v * v; }
    red[tid] = ss; __syncthreads();
    for (int s = 128; s > 0; s >>= 1) { if (tid < s) red[tid] += red[tid + s]; __syncthreads(); }
    float inv = 1.f / fmaxf(sqrtf(red[0]), EPS_);
    for (int c = tid; c < C_; c += 256) g_WnT[k * C_ + c] = w[c * K_ + k] * inv;
}

// ---------------------------------------------------------------------------
// kT2: fused norm + transpose. Block = (n, 32 hw), full C.
// Computes inv, writes g_inv + feature[n][hw][c] = x*inv.
// smem: xs[512][33] f32 (67584B) + inv[32] + part[256]
// ---------------------------------------------------------------------------
#define T2_SMEM (512 * 33 * 4 + 32 * 4 + 256 * 4)

__global__ void __launch_bounds__(256) kT2(const float* __restrict__ x, float* __restrict__ feat) {
    float* xs   = (float*)smem_u;
    float* inv  = xs + 512 * 33;
    float* part = inv + 32;

    int n = blockIdx.x >> 5;
    int hw0 = (blockIdx.x & 31) << 5;
    int tid = threadIdx.x;

    // load [512 c][32 hw] coalesced
    const float* xp = x + (size_t)n * C_ * HW_ + hw0;
    #pragma unroll
    for (int it = 0; it < 16; it++) {
        int idx = tid + it * 256;
        int c = idx >> 3, q = idx & 7;
        float4 v = *(const float4*)(xp + (size_t)c * HW_ + 4 * q);
        xs[c * 33 + 4 * q    ] = v.x;
        xs[c * 33 + 4 * q + 1] = v.y;
        xs[c * 33 + 4 * q + 2] = v.z;
        xs[c * 33 + 4 * q + 3] = v.w;
    }
    __syncthreads();
    {
        int j = tid & 31, t = tid >> 5;
        float ss = 0.f;
        #pragma unroll 8
        for (int c = t; c < C_; c += 8) { float v = xs[c * 33 + j]; ss += v * v; }
        part[tid] = ss;
    }
    __syncthreads();
    if (tid < 32) {
        float ss = 0.f;
        #pragma unroll
        for (int t = 0; t < 8; t++) ss += part[t * 32 + tid];
        float iv = 1.f / fmaxf(sqrtf(ss), EPS_);
        inv[tid] = iv;
        g_inv[n * HW_ + hw0 + tid] = iv;
    }
    __syncthreads();
    float* fp = feat + ((size_t)n * HW_ + hw0) * C_;
    #pragma unroll
    for (int it = 0; it < 16; it++) {
        int idx = tid + it * 256;
        int j = idx >> 7, c4 = (idx & 127) * 4;
        float iv = inv[j];
        float4 v;
        v.x = xs[(c4 + 0) * 33 + j] * iv;
        v.y = xs[(c4 + 1) * 33 + j] * iv;
        v.z = xs[(c4 + 2) * 33 + j] * iv;
        v.w = xs[(c4 + 3) * 33 + j] * iv;
        *(float4*)(fp + (size_t)j * C_ + c4) = v;
    }
}

// ---------------------------------------------------------------------------
// kG1: D[128hw][64k] = feat @ WnT^T (contraction c), split-bf16 3-pass,
// ldmatrix fragment loads. Epilogue: sa_logits + softmax -> g_a.
// smem: Ahi|Alo (128*72*2 each) Bhi|Blo (64*72*2 each) = 55296; ls aliases;
//       bias @55296 -> 55552 bytes
// ---------------------------------------------------------------------------
#define G1_ALO  18432
#define G1_BHI  36864
#define G1_BLO  46080
#define G1_BIAS 55296
#define G1_SMEM 55552

__global__ void __launch_bounds__(256, 2)
kG1(const float* __restrict__ feat, const float* __restrict__ bias, float* __restrict__ sa) {
    char* sm  = smem_u;
    char* Ahi = sm;
    char* Alo = sm + G1_ALO;
    char* Bhi = sm + G1_BHI;
    char* Blo = sm + G1_BLO;
    float* ls  = (float*)sm;
    float* bsm = (float*)(sm + G1_BIAS);

    uint32_t uAhi = s2u(Ahi), uAlo = s2u(Alo), uBhi = s2u(Bhi), uBlo = s2u(Blo);

    int tid = threadIdx.x, wid = tid >> 5, lane = tid & 31;
    int g = lane >> 2, t = lane & 3;
    int row0 = wid * 16;
    int n = blockIdx.x >> 3, hw0 = (blockIdx.x & 7) << 7;

    // lane-static ldmatrix row offsets (bf16 units)
    int arow = (row0 + (lane & 15)) * 72 + ((lane >> 4) << 3);
    int brow = ((lane & 7) + ((lane >> 4) << 3)) * 72 + (((lane >> 3) & 1) << 3);

    if (tid < K_) bsm[tid] = bias[tid];

    float acc[8][4];
    #pragma unroll
    for (int nb = 0; nb < 8; nb++)
        #pragma unroll
        for (int i = 0; i < 4; i++) acc[nb][i] = 0.f;

    for (int cc = 0; cc < C_; cc += 64) {
        __syncthreads();
        #pragma unroll
        for (int it = 0; it < 8; it++) {
            int idx = tid + it * 256;
            int row = idx >> 4, q = idx & 15;
            float4 v = *(const float4*)(feat + ((size_t)(n * HW_ + hw0 + row)) * C_ + cc + 4 * q);
            store_split(Ahi, Alo, (uint32_t)(row * 72 + 4 * q) * 2, v);
        }
        #pragma unroll
        for (int it = 0; it < 4; it++) {
            int idx = tid + it * 256;
            int row = idx >> 4, q = idx & 15;
            float4 v = *(const float4*)(g_WnT + row * C_ + cc + 4 * q);
            store_split(Bhi, Blo, (uint32_t)(row * 72 + 4 * q) * 2, v);
        }
        __syncthreads();
        #pragma unroll
        for (int kk = 0; kk < 64; kk += 16) {
            uint32_t ah0, ah1, ah2, ah3, al0, al1, al2, al3;
            ldsm_x4(ah0, ah1, ah2, ah3, uAhi + (uint32_t)(arow + kk) * 2);
            ldsm_x4(al0, al1, al2, al3, uAlo + (uint32_t)(arow + kk) * 2);
            #pragma unroll
            for (int nb2 = 0; nb2 < 4; nb2++) {
                uint32_t off = (uint32_t)(nb2 * 16 * 72 + brow + kk) * 2;
                uint32_t b0, b1, b2, b3;
                ldsm_x4(b0, b1, b2, b3, uBhi + off);
                mma16816(acc[2 * nb2    ], ah0, ah1, ah2, ah3, b0, b1);
                mma16816(acc[2 * nb2 + 1], ah0, ah1, ah2, ah3, b2, b3);
                mma16816(acc[2 * nb2    ], al0, al1, al2, al3, b0, b1);
                mma16816(acc[2 * nb2 + 1], al0, al1, al2, al3, b2, b3);
                uint32_t c0, c1, c2, c3;
                ldsm_x4(c0, c1, c2, c3, uBlo + off);
                mma16816(acc[2 * nb2    ], ah0, ah1, ah2, ah3, c0, c1);
                mma16816(acc[2 * nb2 + 1], ah0, ah1, ah2, ah3, c2, c3);
            }
        }
    }
    __syncthreads();
    #pragma unroll
    for (int nb = 0; nb < 8; nb++) {
        int col = nb * 8 + 2 * t;
        ls[(row0 + g    ) * 67 + col    ] = acc[nb][0];
        ls[(row0 + g    ) * 67 + col + 1] = acc[nb][1];
        ls[(row0 + g + 8) * 67 + col    ] = acc[nb][2];
        ls[(row0 + g + 8) * 67 + col + 1] = acc[nb][3];
    }
    __syncthreads();
    if (tid < 128) {
        int hw = hw0 + tid;
        float f[64];
        float m = -1e30f;
        float* sp = sa + (size_t)n * K_ * HW_ + hw;
        #pragma unroll
        for (int k = 0; k < K_; k++) {
            float raw = ls[tid * 67 + k];
            sp[(size_t)k * HW_] = raw;
            float v = (raw + bsm[k]) * ALPHA_;
            f[k] = v;
            m = fmaxf(m, v);
        }
        float s = 0.f;
        #pragma unroll
        for (int k = 0; k < K_; k++) { float e = __expf(f[k] - m); f[k] = e; s += e; }
        float is = 1.f / s;
        float* ap = g_a + (size_t)n * K_ * HW_ + hw;
        #pragma unroll
        for (int k = 0; k < K_; k++) ap[(size_t)k * HW_] = f[k] * is;
    }
}

// ---------------------------------------------------------------------------
// kAsum: g_asum[n][k] = sum_h a[n][k][h]
// ---------------------------------------------------------------------------
__global__ void kAsum() {
    __shared__ float red[256];
    int n = blockIdx.x, tid = threadIdx.x;
    int k = tid >> 2, q = tid & 3;
    const float4* ap = (const float4*)(g_a + (size_t)n * K_ * HW_ + (size_t)k * HW_ + q * 256);
    float s = 0.f;
    #pragma unroll 8
    for (int i = 0; i < 64; i++) { float4 v = ap[i]; s += (v.x + v.y) + (v.z + v.w); }
    red[tid] = s;
    __syncthreads();
    if (tid < K_)
        g_asum[n * K_ + tid] = (red[tid * 4] + red[tid * 4 + 1]) + (red[tid * 4 + 2] + red[tid * 4 + 3]);
}

// ---------------------------------------------------------------------------
// kG2: D[128c][64k] = (x*inv) @ a^T (contraction h), split-bf16 3-pass, ldmatrix.
// Epilogue: subtract asum*W, write raw vlad + ssq partials.
// ---------------------------------------------------------------------------
#define G2_ASUM 55296
#define G2_IVS  55552
#define G2_SMEM 59648

__global__ void __launch_bounds__(256, 2)
kG2(const float* __restrict__ x, const float* __restrict__ w, float* __restrict__ vlad) {
    char* sm  = smem_u;
    char* Ahi = sm;
    char* Alo = sm + G1_ALO;
    char* Bhi = sm + G1_BHI;
    char* Blo = sm + G1_BLO;
    float* ls   = (float*)sm;
    float* asum = (float*)(sm + G2_ASUM);
    float* ivs  = (float*)(sm + G2_IVS);

    uint32_t uAhi = s2u(Ahi), uAlo = s2u(Alo), uBhi = s2u(Bhi), uBlo = s2u(Blo);

    int tid = threadIdx.x, wid = tid >> 5, lane = tid & 31;
    int g = lane >> 2, t = lane & 3;
    int row0 = wid * 16;
    int n = blockIdx.x >> 2, ct = blockIdx.x & 3;
    int c0b = ct << 7;

    int arow = (row0 + (lane & 15)) * 72 + ((lane >> 4) << 3);
    int brow = ((lane & 7) + ((lane >> 4) << 3)) * 72 + (((lane >> 3) & 1) << 3);

    if (tid < K_) asum[tid] = g_asum[n * K_ + tid];
    *(float4*)(ivs + 4 * tid) = *(const float4*)(g_inv + n * HW_ + 4 * tid);

    float acc[8][4];
    #pragma unroll
    for (int nb = 0; nb < 8; nb++)
        #pragma unroll
        for (int i = 0; i < 4; i++) acc[nb][i] = 0.f;

    __syncthreads();
    for (int h0 = 0; h0 < HW_; h0 += 64) {
        __syncthreads();
        #pragma unroll
        for (int it = 0; it < 8; it++) {
            int idx = tid + it * 256;
            int row = idx >> 4, q = idx & 15;
            float4 v = *(const float4*)(x + ((size_t)n * C_ + c0b + row) * HW_ + h0 + 4 * q);
            float4 iv = *(const float4*)(ivs + h0 + 4 * q);
            v.x *= iv.x; v.y *= iv.y; v.z *= iv.z; v.w *= iv.w;
            store_split(Ahi, Alo, (uint32_t)(row * 72 + 4 * q) * 2, v);
        }
        #pragma unroll
        for (int it = 0; it < 4; it++) {
            int idx = tid + it * 256;
            int row = idx >> 4, q = idx & 15;
            float4 v = *(const float4*)(g_a + (size_t)n * K_ * HW_ + (size_t)row * HW_ + h0 + 4 * q);
            store_split(Bhi, Blo, (uint32_t)(row * 72 + 4 * q) * 2, v);
        }
        __syncthreads();
        #pragma unroll
        for (int kk = 0; kk < 64; kk += 16) {
            uint32_t ah0, ah1, ah2, ah3, al0, al1, al2, al3;
            ldsm_x4(ah0, ah1, ah2, ah3, uAhi + (uint32_t)(arow + kk) * 2);
            ldsm_x4(al0, al1, al2, al3, uAlo + (uint32_t)(arow + kk) * 2);
            #pragma unroll
            for (int nb2 = 0; nb2 < 4; nb2++) {
                uint32_t off = (uint32_t)(nb2 * 16 * 72 + brow + kk) * 2;
                uint32_t b0, b1, b2, b3;
                ldsm_x4(b0, b1, b2, b3, uBhi + off);
                mma16816(acc[2 * nb2    ], ah0, ah1, ah2, ah3, b0, b1);
                mma16816(acc[2 * nb2 + 1], ah0, ah1, ah2, ah3, b2, b3);
                mma16816(acc[2 * nb2    ], al0, al1, al2, al3, b0, b1);
                mma16816(acc[2 * nb2 + 1], al0, al1, al2, al3, b2, b3);
                uint32_t c0, c1, c2, c3;
                ldsm_x4(c0, c1, c2, c3, uBlo + off);
                mma16816(acc[2 * nb2    ], ah0, ah1, ah2, ah3, c0, c1);
                mma16816(acc[2 * nb2 + 1], ah0, ah1, ah2, ah3, c2, c3);
            }
        }
    }
    __syncthreads();
    #pragma unroll
    for (int nb = 0; nb < 8; nb++) {
        int col = nb * 8 + 2 * t;
        ls[(row0 + g    ) * 67 + col    ] = acc[nb][0];
        ls[(row0 + g    ) * 67 + col + 1] = acc[nb][1];
        ls[(row0 + g + 8) * 67 + col    ] = acc[nb][2];
        ls[(row0 + g + 8) * 67 + col + 1] = acc[nb][3];
    }
    __syncthreads();
    if (tid < 128) {
        int c = c0b + tid;
        float f[64];
        #pragma unroll
        for (int i = 0; i < 16; i++) {
            float4 wv = *(const float4*)(w + (size_t)c * K_ + 4 * i);
            f[4 * i    ] = ls[tid * 67 + 4 * i    ] - asum[4 * i    ] * wv.x;
            f[4 * i + 1] = ls[tid * 67 + 4 * i + 1] - asum[4 * i + 1] * wv.y;
            f[4 * i + 2] = ls[tid * 67 + 4 * i + 2] - asum[4 * i + 2] * wv.z;
            f[4 * i + 3] = ls[tid * 67 + 4 * i + 3] - asum[4 * i + 3] * wv.w;
        }
        float* vp = vlad + (size_t)n * K_ * C_ + c;
        #pragma unroll
        for (int k = 0; k < K_; k++) {
            vp[(size_t)k * C_] = f[k];
            ls[tid * 67 + k] = f[k];
        }
    }
    __syncthreads();
    if (tid < K_) {
        float s = 0.f;
        #pragma unroll 4
        for (int c = 0; c < 128; c++) { float v = ls[c * 67 + tid]; s += v * v; }
        g_ssq[(n * K_ + tid) * 4 + ct] = s;
    }
}

// ---------------------------------------------------------------------------
// k3: row L2 norm of vlad
// ---------------------------------------------------------------------------
__global__ void k3_kernel(float* __restrict__ vlad) {
    int row = blockIdx.x;
    const float* sp = g_ssq + row * 4;
    float ssq = (sp[0] + sp[1]) + (sp[2] + sp[3]);
    float iv = 1.f / fmaxf(sqrtf(ssq), EPS_);
    float4* vp = (float4*)(vlad + (size_t)row * C_);
    float4 v = vp[threadIdx.x];
    v.x *= iv; v.y *= iv; v.z *= iv; v.w *= iv;
    vp[threadIdx.x] = v;
}

// ---------------------------------------------------------------------------
extern "C" void kernel_launch(void* const* d_in, const int* in_sizes, int n_in,
                              void* d_out, int out_size) {
    const float* x    = (const float*)d_in[0];   // [64,512,32,32]
    const float* w    = (const float*)d_in[1];   // [512,64]
    const float* bias = (const float*)d_in[2];   // [64]
    float* out  = (float*)d_out;
    float* vlad = out;                                    // [64, 64*512]
    float* sa   = out + (size_t)N_ * K_ * C_;             // [64, 64, 1024]
    float* feat = sa  + (size_t)N_ * K_ * HW_;            // [64, 1024, 512]

    cudaFuncSetAttribute(kT2, cudaFuncAttributeMaxDynamicSharedMemorySize, T2_SMEM);
    cudaFuncSetAttribute(kG1, cudaFuncAttributeMaxDynamicSharedMemorySize, G1_SMEM);
    cudaFuncSetAttribute(kG2, cudaFuncAttributeMaxDynamicSharedMemorySize, G2_SMEM);

    k0_kernel<<<K_, 256>>>(w);
    kT2<<<N_ * 32, 256, T2_SMEM>>>(x, feat);
    kG1<<<N_ * 8, 256, G1_SMEM>>>(feat, bias, sa);
    kAsum<<<N_, 256>>>();
    kG2<<<N_ * 4, 256, G2_SMEM>>>(x, w, vlad);
    k3_kernel<<<N_ * K_, 128>>>(vlad);
}

// round 13
// speedup vs baseline: 3.5554x; 1.1033x over previous
#include <cuda_runtime.h>
#include <cuda_bf16.h>
#include <math.h>
#include <stdint.h>

#define N_    64
#define C_    512
#define HW_   1024
#define K_    64
#define ALPHA_ 50.0f
#define EPS_  1e-12f

typedef unsigned long long ull;

extern __shared__ char smem_u[];

// static scratch
__device__ __align__(16) uint32_t g_W2[K_ * C_];                 // packed (hi<<16|lo) split Wn^T [k][c]
__device__ __align__(16) float    g_inv[N_ * HW_];               // 1/||x[n,:,hw]||
__device__ __align__(16) uint32_t g_a2[(size_t)N_ * K_ * HW_];   // packed split soft-assign [n][k][hw]
__device__ __align__(16) float    g_asum_part[N_ * 8 * K_];      // asum partials per hw-block
__device__ __align__(16) float    g_ssq[N_ * K_ * 4];

// ---------------------------------------------------------------------------
__device__ __forceinline__ uint32_t s2u(const void* p) {
    uint32_t a;
    asm("{ .reg .u64 t; cvta.to.shared.u64 t, %1; cvt.u32.u64 %0, t; }" : "=r"(a) : "l"(p));
    return a;
}
__device__ __forceinline__ void mma16816(float* c, uint32_t a0, uint32_t a1,
                                         uint32_t a2, uint32_t a3,
                                         uint32_t b0, uint32_t b1) {
    asm volatile(
        "mma.sync.aligned.m16n8k16.row.col.f32.bf16.bf16.f32 "
        "{%0,%1,%2,%3}, {%4,%5,%6,%7}, {%8,%9}, {%0,%1,%2,%3};"
        : "+f"(c[0]), "+f"(c[1]), "+f"(c[2]), "+f"(c[3])
        : "r"(a0), "r"(a1), "r"(a2), "r"(a3), "r"(b0), "r"(b1));
}
__device__ __forceinline__ void ldsm_x4(uint32_t& r0, uint32_t& r1, uint32_t& r2,
                                        uint32_t& r3, uint32_t addr) {
    asm volatile("ldmatrix.sync.aligned.m8n8.x4.shared.b16 {%0,%1,%2,%3}, [%4];"
                 : "=r"(r0), "=r"(r1), "=r"(r2), "=r"(r3) : "r"(addr));
}
// f32 -> packed (hi<<16 | lo) bf16 split
__device__ __forceinline__ uint32_t pack_split(float v) {
    __nv_bfloat16 h = __float2bfloat16_rn(v);
    __nv_bfloat16 l = __float2bfloat16_rn(v - __bfloat162float(h));
    return ((uint32_t)__bfloat16_as_ushort(h) << 16) | (uint32_t)__bfloat16_as_ushort(l);
}
// split f32 -> (hi, lo) bf16 quads into padded smem rows
__device__ __forceinline__ void store_split(char* hi, char* lo, uint32_t byte_off, float4 v) {
    float f[4] = {v.x, v.y, v.z, v.w};
    ull ph = 0, pl = 0;
    #pragma unroll
    for (int i = 0; i < 4; i++) {
        uint32_t p = pack_split(f[i]);
        ph |= (ull)(p >> 16)     << (16 * i);
        pl |= (ull)(p & 0xFFFFu) << (16 * i);
    }
    *(ull*)(hi + byte_off) = ph;
    *(ull*)(lo + byte_off) = pl;
}
// unzip packed uint4 (4 elements) into hi/lo 8-byte halves
__device__ __forceinline__ void unzip4(uint4 p, char* hi, char* lo, uint32_t byte_off) {
    uint32_t h0 = __byte_perm(p.x, p.y, 0x7632);
    uint32_t h1 = __byte_perm(p.z, p.w, 0x7632);
    uint32_t l0 = __byte_perm(p.x, p.y, 0x5410);
    uint32_t l1 = __byte_perm(p.z, p.w, 0x5410);
    *(ull*)(hi + byte_off) = ((ull)h1 << 32) | h0;
    *(ull*)(lo + byte_off) = ((ull)l1 << 32) | l0;
}

// ---------------------------------------------------------------------------
// k0: g_W2[k][c] = packed split of W[c][k]/||W[:,k]||
// ---------------------------------------------------------------------------
__global__ void k0_kernel(const float* __restrict__ w) {
    int k = blockIdx.x, tid = threadIdx.x;
    __shared__ float red[256];
    float ss = 0.f;
    for (int c = tid; c < C_; c += 256) { float v = w[c * K_ + k]; ss += v * v; }
    red[tid] = ss; __syncthreads();
    for (int s = 128; s > 0; s >>= 1) { if (tid < s) red[tid] += red[tid + s]; __syncthreads(); }
    float inv = 1.f / fmaxf(sqrtf(red[0]), EPS_);
    for (int c = tid; c < C_; c += 256) g_W2[k * C_ + c] = pack_split(w[c * K_ + k] * inv);
}

// ---------------------------------------------------------------------------
// kT2: fused norm + transpose. Block = (n, 32 hw), full C.
// ---------------------------------------------------------------------------
#define T2_SMEM (512 * 33 * 4 + 32 * 4 + 256 * 4)

__global__ void __launch_bounds__(256) kT2(const float* __restrict__ x, float* __restrict__ feat) {
    float* xs   = (float*)smem_u;
    float* inv  = xs + 512 * 33;
    float* part = inv + 32;

    int n = blockIdx.x >> 5;
    int hw0 = (blockIdx.x & 31) << 5;
    int tid = threadIdx.x;

    const float* xp = x + (size_t)n * C_ * HW_ + hw0;
    #pragma unroll
    for (int it = 0; it < 16; it++) {
        int idx = tid + it * 256;
        int c = idx >> 3, q = idx & 7;
        float4 v = *(const float4*)(xp + (size_t)c * HW_ + 4 * q);
        xs[c * 33 + 4 * q    ] = v.x;
        xs[c * 33 + 4 * q + 1] = v.y;
        xs[c * 33 + 4 * q + 2] = v.z;
        xs[c * 33 + 4 * q + 3] = v.w;
    }
    __syncthreads();
    {
        int j = tid & 31, t = tid >> 5;
        float ss = 0.f;
        #pragma unroll 8
        for (int c = t; c < C_; c += 8) { float v = xs[c * 33 + j]; ss += v * v; }
        part[tid] = ss;
    }
    __syncthreads();
    if (tid < 32) {
        float ss = 0.f;
        #pragma unroll
        for (int t = 0; t < 8; t++) ss += part[t * 32 + tid];
        float iv = 1.f / fmaxf(sqrtf(ss), EPS_);
        inv[tid] = iv;
        g_inv[n * HW_ + hw0 + tid] = iv;
    }
    __syncthreads();
    float* fp = feat + ((size_t)n * HW_ + hw0) * C_;
    #pragma unroll
    for (int it = 0; it < 16; it++) {
        int idx = tid + it * 256;
        int j = idx >> 7, c4 = (idx & 127) * 4;
        float iv = inv[j];
        float4 v;
        v.x = xs[(c4 + 0) * 33 + j] * iv;
        v.y = xs[(c4 + 1) * 33 + j] * iv;
        v.z = xs[(c4 + 2) * 33 + j] * iv;
        v.w = xs[(c4 + 3) * 33 + j] * iv;
        *(float4*)(fp + (size_t)j * C_ + c4) = v;
    }
}

// ---------------------------------------------------------------------------
// kG1: D[128hw][64k] = feat @ WnT^T, split-bf16 3-pass, ldmatrix.
// Epilogue: sa_logits + softmax -> g_a2 (packed) + asum partials.
// ---------------------------------------------------------------------------
#define G1_ALO  18432
#define G1_BHI  36864
#define G1_BLO  46080
#define G1_RED2 36864           // post-GEMM alias (2112 floats)
#define G1_BIAS 55296
#define G1_SMEM 55552

__global__ void __launch_bounds__(256, 2)
kG1(const float* __restrict__ feat, const float* __restrict__ bias, float* __restrict__ sa) {
    char* sm  = smem_u;
    char* Ahi = sm;
    char* Alo = sm + G1_ALO;
    char* Bhi = sm + G1_BHI;
    char* Blo = sm + G1_BLO;
    float* ls   = (float*)sm;
    float* red2 = (float*)(sm + G1_RED2);
    float* bsm  = (float*)(sm + G1_BIAS);

    uint32_t uAhi = s2u(Ahi), uAlo = s2u(Alo), uBhi = s2u(Bhi), uBlo = s2u(Blo);

    int tid = threadIdx.x, wid = tid >> 5, lane = tid & 31;
    int g = lane >> 2, t = lane & 3;
    int row0 = wid * 16;
    int n = blockIdx.x >> 3, blk = blockIdx.x & 7;
    int hw0 = blk << 7;

    int arow = (row0 + (lane & 15)) * 72 + ((lane >> 4) << 3);
    int brow = ((lane & 7) + ((lane >> 4) << 3)) * 72 + (((lane >> 3) & 1) << 3);

    if (tid < K_) bsm[tid] = bias[tid];

    float acc[8][4];
    #pragma unroll
    for (int nb = 0; nb < 8; nb++)
        #pragma unroll
        for (int i = 0; i < 4; i++) acc[nb][i] = 0.f;

    for (int cc = 0; cc < C_; cc += 64) {
        __syncthreads();
        // A: feat f32 -> split (128 rows x 64 c)
        #pragma unroll
        for (int it = 0; it < 8; it++) {
            int idx = tid + it * 256;
            int row = idx >> 4, q = idx & 15;
            float4 v = *(const float4*)(feat + ((size_t)(n * HW_ + hw0 + row)) * C_ + cc + 4 * q);
            store_split(Ahi, Alo, (uint32_t)(row * 72 + 4 * q) * 2, v);
        }
        // B: packed W -> unzip copy (64 rows x 64 c)
        #pragma unroll
        for (int it = 0; it < 4; it++) {
            int idx = tid + it * 256;
            int row = idx >> 4, q = idx & 15;
            uint4 p = *(const uint4*)(g_W2 + row * C_ + cc + 4 * q);
            unzip4(p, Bhi, Blo, (uint32_t)(row * 72 + 4 * q) * 2);
        }
        __syncthreads();
        #pragma unroll
        for (int kk = 0; kk < 64; kk += 16) {
            uint32_t ah0, ah1, ah2, ah3, al0, al1, al2, al3;
            ldsm_x4(ah0, ah1, ah2, ah3, uAhi + (uint32_t)(arow + kk) * 2);
            ldsm_x4(al0, al1, al2, al3, uAlo + (uint32_t)(arow + kk) * 2);
            #pragma unroll
            for (int nb2 = 0; nb2 < 4; nb2++) {
                uint32_t off = (uint32_t)(nb2 * 16 * 72 + brow + kk) * 2;
                uint32_t b0, b1, b2, b3;
                ldsm_x4(b0, b1, b2, b3, uBhi + off);
                mma16816(acc[2 * nb2    ], ah0, ah1, ah2, ah3, b0, b1);
                mma16816(acc[2 * nb2 + 1], ah0, ah1, ah2, ah3, b2, b3);
                mma16816(acc[2 * nb2    ], al0, al1, al2, al3, b0, b1);
                mma16816(acc[2 * nb2 + 1], al0, al1, al2, al3, b2, b3);
                uint32_t c0, c1, c2, c3;
                ldsm_x4(c0, c1, c2, c3, uBlo + off);
                mma16816(acc[2 * nb2    ], ah0, ah1, ah2, ah3, c0, c1);
                mma16816(acc[2 * nb2 + 1], ah0, ah1, ah2, ah3, c2, c3);
            }
        }
    }
    __syncthreads();
    #pragma unroll
    for (int nb = 0; nb < 8; nb++) {
        int col = nb * 8 + 2 * t;
        ls[(row0 + g    ) * 67 + col    ] = acc[nb][0];
        ls[(row0 + g    ) * 67 + col + 1] = acc[nb][1];
        ls[(row0 + g + 8) * 67 + col    ] = acc[nb][2];
        ls[(row0 + g + 8) * 67 + col + 1] = acc[nb][3];
    }
    __syncthreads();
    if (tid < 128) {
        int hw = hw0 + tid;
        float f[64];
        float m = -1e30f;
        float* sp = sa + (size_t)n * K_ * HW_ + hw;
        #pragma unroll
        for (int k = 0; k < K_; k++) {
            float raw = ls[tid * 67 + k];
            sp[(size_t)k * HW_] = raw;
            float v = (raw + bsm[k]) * ALPHA_;
            f[k] = v;
            m = fmaxf(m, v);
        }
        float s = 0.f;
        #pragma unroll
        for (int k = 0; k < K_; k++) { float e = __expf(f[k] - m); f[k] = e; s += e; }
        float is = 1.f / s;
        #pragma unroll
        for (int k = 0; k < K_; k++) ls[tid * 67 + k] = f[k] * is;   // overwrite with a
    }
    __syncthreads();
    // repack a -> g_a2 (packed split), accumulate asum partials
    {
        uint32_t* ap = g_a2 + (size_t)n * K_ * HW_ + hw0;
        #pragma unroll
        for (int it = 0; it < 8; it++) {
            int idx = tid + it * 256;
            int k = idx >> 5, q = idx & 31;
            float a0 = ls[(4 * q    ) * 67 + k];
            float a1 = ls[(4 * q + 1) * 67 + k];
            float a2v = ls[(4 * q + 2) * 67 + k];
            float a3 = ls[(4 * q + 3) * 67 + k];
            uint4 o;
            o.x = pack_split(a0); o.y = pack_split(a1);
            o.z = pack_split(a2v); o.w = pack_split(a3);
            *(uint4*)(ap + (size_t)k * HW_ + 4 * q) = o;
            red2[k * 33 + q] = (a0 + a1) + (a2v + a3);
        }
    }
    __syncthreads();
    if (tid < K_) {
        float s = 0.f;
        #pragma unroll
        for (int q = 0; q < 32; q++) s += red2[tid * 33 + q];
        g_asum_part[(n * 8 + blk) * K_ + tid] = s;
    }
}

// ---------------------------------------------------------------------------
// kG2: D[128c][64k] = (x*inv) @ a^T, split-bf16 3-pass, ldmatrix.
// B staged by unzipping g_a2. Epilogue: -asum*W, vlad raw + ssq partials.
// ---------------------------------------------------------------------------
#define G2_ASUM 55296
#define G2_IVS  55552
#define G2_SMEM 59648

__global__ void __launch_bounds__(256, 2)
kG2(const float* __restrict__ x, const float* __restrict__ w, float* __restrict__ vlad) {
    char* sm  = smem_u;
    char* Ahi = sm;
    char* Alo = sm + G1_ALO;
    char* Bhi = sm + G1_BHI;
    char* Blo = sm + G1_BLO;
    float* ls   = (float*)sm;
    float* asum = (float*)(sm + G2_ASUM);
    float* ivs  = (float*)(sm + G2_IVS);

    uint32_t uAhi = s2u(Ahi), uAlo = s2u(Alo), uBhi = s2u(Bhi), uBlo = s2u(Blo);

    int tid = threadIdx.x, wid = tid >> 5, lane = tid & 31;
    int g = lane >> 2, t = lane & 3;
    int row0 = wid * 16;
    int n = blockIdx.x >> 2, ct = blockIdx.x & 3;
    int c0b = ct << 7;

    int arow = (row0 + (lane & 15)) * 72 + ((lane >> 4) << 3);
    int brow = ((lane & 7) + ((lane >> 4) << 3)) * 72 + (((lane >> 3) & 1) << 3);

    if (tid < K_) {
        const float* pp = g_asum_part + n * 8 * K_ + tid;
        float s = 0.f;
        #pragma unroll
        for (int b = 0; b < 8; b++) s += pp[b * K_];
        asum[tid] = s;
    }
    *(float4*)(ivs + 4 * tid) = *(const float4*)(g_inv + n * HW_ + 4 * tid);

    float acc[8][4];
    #pragma unroll
    for (int nb = 0; nb < 8; nb++)
        #pragma unroll
        for (int i = 0; i < 4; i++) acc[nb][i] = 0.f;

    __syncthreads();
    for (int h0 = 0; h0 < HW_; h0 += 64) {
        __syncthreads();
        // A: x*inv -> split (128 c rows x 64 h)
        #pragma unroll
        for (int it = 0; it < 8; it++) {
            int idx = tid + it * 256;
            int row = idx >> 4, q = idx & 15;
            float4 v = *(const float4*)(x + ((size_t)n * C_ + c0b + row) * HW_ + h0 + 4 * q);
            float4 iv = *(const float4*)(ivs + h0 + 4 * q);
            v.x *= iv.x; v.y *= iv.y; v.z *= iv.z; v.w *= iv.w;
            store_split(Ahi, Alo, (uint32_t)(row * 72 + 4 * q) * 2, v);
        }
        // B: packed a -> unzip copy (64 k rows x 64 h)
        #pragma unroll
        for (int it = 0; it < 4; it++) {
            int idx = tid + it * 256;
            int row = idx >> 4, q = idx & 15;
            uint4 p = *(const uint4*)(g_a2 + (size_t)n * K_ * HW_ + (size_t)row * HW_ + h0 + 4 * q);
            unzip4(p, Bhi, Blo, (uint32_t)(row * 72 + 4 * q) * 2);
        }
        __syncthreads();
        #pragma unroll
        for (int kk = 0; kk < 64; kk += 16) {
            uint32_t ah0, ah1, ah2, ah3, al0, al1, al2, al3;
            ldsm_x4(ah0, ah1, ah2, ah3, uAhi + (uint32_t)(arow + kk) * 2);
            ldsm_x4(al0, al1, al2, al3, uAlo + (uint32_t)(arow + kk) * 2);
            #pragma unroll
            for (int nb2 = 0; nb2 < 4; nb2++) {
                uint32_t off = (uint32_t)(nb2 * 16 * 72 + brow + kk) * 2;
                uint32_t b0, b1, b2, b3;
                ldsm_x4(b0, b1, b2, b3, uBhi + off);
                mma16816(acc[2 * nb2    ], ah0, ah1, ah2, ah3, b0, b1);
                mma16816(acc[2 * nb2 + 1], ah0, ah1, ah2, ah3, b2, b3);
                mma16816(acc[2 * nb2    ], al0, al1, al2, al3, b0, b1);
                mma16816(acc[2 * nb2 + 1], al0, al1, al2, al3, b2, b3);
                uint32_t c0, c1, c2, c3;
                ldsm_x4(c0, c1, c2, c3, uBlo + off);
                mma16816(acc[2 * nb2    ], ah0, ah1, ah2, ah3, c0, c1);
                mma16816(acc[2 * nb2 + 1], ah0, ah1, ah2, ah3, c2, c3);
            }
        }
    }
    __syncthreads();
    #pragma unroll
    for (int nb = 0; nb < 8; nb++) {
        int col = nb * 8 + 2 * t;
        ls[(row0 + g    ) * 67 + col    ] = acc[nb][0];
        ls[(row0 + g    ) * 67 + col + 1] = acc[nb][1];
        ls[(row0 + g + 8) * 67 + col    ] = acc[nb][2];
        ls[(row0 + g + 8) * 67 + col + 1] = acc[nb][3];
    }
    __syncthreads();
    if (tid < 128) {
        int c = c0b + tid;
        float f[64];
        #pragma unroll
        for (int i = 0; i < 16; i++) {
            float4 wv = *(const float4*)(w + (size_t)c * K_ + 4 * i);
            f[4 * i    ] = ls[tid * 67 + 4 * i    ] - asum[4 * i    ] * wv.x;
            f[4 * i + 1] = ls[tid * 67 + 4 * i + 1] - asum[4 * i + 1] * wv.y;
            f[4 * i + 2] = ls[tid * 67 + 4 * i + 2] - asum[4 * i + 2] * wv.z;
            f[4 * i + 3] = ls[tid * 67 + 4 * i + 3] - asum[4 * i + 3] * wv.w;
        }
        float* vp = vlad + (size_t)n * K_ * C_ + c;
        #pragma unroll
        for (int k = 0; k < K_; k++) {
            vp[(size_t)k * C_] = f[k];
            ls[tid * 67 + k] = f[k];
        }
    }
    __syncthreads();
    if (tid < K_) {
        float s = 0.f;
        #pragma unroll 4
        for (int c = 0; c < 128; c++) { float v = ls[c * 67 + tid]; s += v * v; }
        g_ssq[(n * K_ + tid) * 4 + ct] = s;
    }
}

// ---------------------------------------------------------------------------
// k3: row L2 norm of vlad
// ---------------------------------------------------------------------------
__global__ void k3_kernel(float* __restrict__ vlad) {
    int row = blockIdx.x;
    const float* sp = g_ssq + row * 4;
    float ssq = (sp[0] + sp[1]) + (sp[2] + sp[3]);
    float iv = 1.f / fmaxf(sqrtf(ssq), EPS_);
    float4* vp = (float4*)(vlad + (size_t)row * C_);
    float4 v = vp[threadIdx.x];
    v.x *= iv; v.y *= iv; v.z *= iv; v.w *= iv;
    vp[threadIdx.x] = v;
}

// ---------------------------------------------------------------------------
extern "C" void kernel_launch(void* const* d_in, const int* in_sizes, int n_in,
                              void* d_out, int out_size) {
    const float* x    = (const float*)d_in[0];   // [64,512,32,32]
    const float* w    = (const float*)d_in[1];   // [512,64]
    const float* bias = (const float*)d_in[2];   // [64]
    float* out  = (float*)d_out;
    float* vlad = out;                                    // [64, 64*512]
    float* sa   = out + (size_t)N_ * K_ * C_;             // [64, 64, 1024]
    float* feat = sa  + (size_t)N_ * K_ * HW_;            // [64, 1024, 512]

    cudaFuncSetAttribute(kT2, cudaFuncAttributeMaxDynamicSharedMemorySize, T2_SMEM);
    cudaFuncSetAttribute(kG1, cudaFuncAttributeMaxDynamicSharedMemorySize, G1_SMEM);
    cudaFuncSetAttribute(kG2, cudaFuncAttributeMaxDynamicSharedMemorySize, G2_SMEM);

    k0_kernel<<<K_, 256>>>(w);
    kT2<<<N_ * 32, 256, T2_SMEM>>>(x, feat);
    kG1<<<N_ * 8, 256, G1_SMEM>>>(feat, bias, sa);
    kG2<<<N_ * 4, 256, G2_SMEM>>>(x, w, vlad);
    k3_kernel<<<N_ * K_, 128>>>(vlad);
}

// round 14
// speedup vs baseline: 3.7989x; 1.0685x over previous
#include <cuda_runtime.h>
#include <cuda_bf16.h>
#include <math.h>
#include <stdint.h>

#define N_    64
#define C_    512
#define HW_   1024
#define K_    64
#define ALPHA_ 50.0f
#define EPS_  1e-12f

typedef unsigned short u16;

extern __shared__ char smem_u[];

// static scratch (split bf16 operand caches)
__device__ __align__(16) u16   g_whi[K_ * C_];
__device__ __align__(16) u16   g_wlo[K_ * C_];
__device__ __align__(16) u16   g_xhi[(size_t)N_ * C_ * HW_];
__device__ __align__(16) u16   g_xlo[(size_t)N_ * C_ * HW_];
__device__ __align__(16) u16   g_ahi[(size_t)N_ * K_ * HW_];
__device__ __align__(16) u16   g_alo[(size_t)N_ * K_ * HW_];
__device__ __align__(16) float g_asum_part[N_ * 8 * K_];
__device__ __align__(16) float g_ssq[N_ * K_ * 4];

// ---------------------------------------------------------------------------
__device__ __forceinline__ uint32_t s2u(const void* p) {
    uint32_t a;
    asm("{ .reg .u64 t; cvta.to.shared.u64 t, %1; cvt.u32.u64 %0, t; }" : "=r"(a) : "l"(p));
    return a;
}
__device__ __forceinline__ void mma16816(float* c, uint32_t a0, uint32_t a1,
                                         uint32_t a2, uint32_t a3,
                                         uint32_t b0, uint32_t b1) {
    asm volatile(
        "mma.sync.aligned.m16n8k16.row.col.f32.bf16.bf16.f32 "
        "{%0,%1,%2,%3}, {%4,%5,%6,%7}, {%8,%9}, {%0,%1,%2,%3};"
        : "+f"(c[0]), "+f"(c[1]), "+f"(c[2]), "+f"(c[3])
        : "r"(a0), "r"(a1), "r"(a2), "r"(a3), "r"(b0), "r"(b1));
}
__device__ __forceinline__ void ldsm_x4(uint32_t& r0, uint32_t& r1, uint32_t& r2,
                                        uint32_t& r3, uint32_t addr) {
    asm volatile("ldmatrix.sync.aligned.m8n8.x4.shared.b16 {%0,%1,%2,%3}, [%4];"
                 : "=r"(r0), "=r"(r1), "=r"(r2), "=r"(r3) : "r"(addr));
}
__device__ __forceinline__ void ldsm_x4_t(uint32_t& r0, uint32_t& r1, uint32_t& r2,
                                          uint32_t& r3, uint32_t addr) {
    asm volatile("ldmatrix.sync.aligned.m8n8.x4.trans.shared.b16 {%0,%1,%2,%3}, [%4];"
                 : "=r"(r0), "=r"(r1), "=r"(r2), "=r"(r3) : "r"(addr));
}
__device__ __forceinline__ void cpa(uint32_t dst, const u16* src) {
    asm volatile("cp.async.cg.shared.global [%0], [%1], 16;"
                 :: "r"(dst), "l"((size_t)__cvta_generic_to_global(src)) : "memory");
}
#define CP_COMMIT() asm volatile("cp.async.commit_group;" ::: "memory")
#define CP_WAIT1()  asm volatile("cp.async.wait_group 1;" ::: "memory")
#define CP_WAIT0()  asm volatile("cp.async.wait_group 0;" ::: "memory")

__device__ __forceinline__ void split1(float v, u16& h, u16& l) {
    __nv_bfloat16 bh = __float2bfloat16_rn(v);
    __nv_bfloat16 bl = __float2bfloat16_rn(v - __bfloat162float(bh));
    h = __bfloat16_as_ushort(bh);
    l = __bfloat16_as_ushort(bl);
}

// ---------------------------------------------------------------------------
// k0: column-normalize W, emit split bf16 Wn^T [k][c]
// ---------------------------------------------------------------------------
__global__ void k0_kernel(const float* __restrict__ w) {
    int k = blockIdx.x, tid = threadIdx.x;
    __shared__ float red[256];
    float ss = 0.f;
    for (int c = tid; c < C_; c += 256) { float v = w[c * K_ + k]; ss += v * v; }
    red[tid] = ss; __syncthreads();
    for (int s = 128; s > 0; s >>= 1) { if (tid < s) red[tid] += red[tid + s]; __syncthreads(); }
    float inv = 1.f / fmaxf(sqrtf(red[0]), EPS_);
    for (int c = tid; c < C_; c += 256) {
        u16 h, l;
        split1(w[c * K_ + k] * inv, h, l);
        g_whi[k * C_ + c] = h;
        g_wlo[k * C_ + c] = l;
    }
}

// ---------------------------------------------------------------------------
// kT2: fused norm + transpose + split emit. Block = (n, 32 hw), full C.
// Writes feature f32 [n][hw][c] (output) and g_xhi/g_xlo [n][c][hw] (split).
// ---------------------------------------------------------------------------
#define T2_SMEM (512 * 33 * 4 + 32 * 4 + 256 * 4)

__global__ void __launch_bounds__(256) kT2(const float* __restrict__ x, float* __restrict__ feat) {
    float* xs   = (float*)smem_u;
    float* inv  = xs + 512 * 33;
    float* part = inv + 32;

    int n = blockIdx.x >> 5;
    int hw0 = (blockIdx.x & 31) << 5;
    int tid = threadIdx.x;

    const float* xp = x + (size_t)n * C_ * HW_ + hw0;
    #pragma unroll
    for (int it = 0; it < 16; it++) {
        int idx = tid + it * 256;
        int c = idx >> 3, q = idx & 7;
        float4 v = *(const float4*)(xp + (size_t)c * HW_ + 4 * q);
        xs[c * 33 + 4 * q    ] = v.x;
        xs[c * 33 + 4 * q + 1] = v.y;
        xs[c * 33 + 4 * q + 2] = v.z;
        xs[c * 33 + 4 * q + 3] = v.w;
    }
    __syncthreads();
    {
        int j = tid & 31, t = tid >> 5;
        float ss = 0.f;
        #pragma unroll 8
        for (int c = t; c < C_; c += 8) { float v = xs[c * 33 + j]; ss += v * v; }
        part[tid] = ss;
    }
    __syncthreads();
    if (tid < 32) {
        float ss = 0.f;
        #pragma unroll
        for (int t = 0; t < 8; t++) ss += part[t * 32 + tid];
        inv[tid] = 1.f / fmaxf(sqrtf(ss), EPS_);
    }
    __syncthreads();
    // feature f32 output [hw][c]
    float* fp = feat + ((size_t)n * HW_ + hw0) * C_;
    #pragma unroll
    for (int it = 0; it < 16; it++) {
        int idx = tid + it * 256;
        int j = idx >> 7, c4 = (idx & 127) * 4;
        float iv = inv[j];
        float4 v;
        v.x = xs[(c4 + 0) * 33 + j] * iv;
        v.y = xs[(c4 + 1) * 33 + j] * iv;
        v.z = xs[(c4 + 2) * 33 + j] * iv;
        v.w = xs[(c4 + 3) * 33 + j] * iv;
        *(float4*)(fp + (size_t)j * C_ + c4) = v;
    }
    // split emit [c][hw]
    u16* xh = g_xhi + (size_t)n * C_ * HW_ + hw0;
    u16* xl = g_xlo + (size_t)n * C_ * HW_ + hw0;
    #pragma unroll
    for (int it = 0; it < 32; it++) {
        int idx = tid + it * 256;
        int c = idx >> 4, jp = (idx & 15) * 2;
        float v0 = xs[c * 33 + jp    ] * inv[jp    ];
        float v1 = xs[c * 33 + jp + 1] * inv[jp + 1];
        u16 h0, l0, h1, l1;
        split1(v0, h0, l0);
        split1(v1, h1, l1);
        *(uint32_t*)(xh + (size_t)c * HW_ + jp) = (uint32_t)h0 | ((uint32_t)h1 << 16);
        *(uint32_t*)(xl + (size_t)c * HW_ + jp) = (uint32_t)l0 | ((uint32_t)l1 << 16);
    }
}

// ---------------------------------------------------------------------------
// kG1: D[128hw][64k] = feat @ Wn^T, contraction c. A from g_xhi/g_xlo [c][hw]
// via trans-ldmatrix; B from g_whi/g_wlo. cp.async double-buffered.
// Epilogue: sa_logits + softmax -> g_ahi/g_alo + asum partials.
// stage: AH[64][136] 17408 | AL 17408 | BH[64][72] 9216 | BL 9216 = 53248
// ---------------------------------------------------------------------------
#define S1STG   53248
#define S1_AL   17408
#define S1_BH   34816
#define S1_BL   44032
#define G1_BIAS 106496
#define G1_SMEM 106752

__global__ void __launch_bounds__(256, 2)
kG1(const float* __restrict__ bias, float* __restrict__ sa) {
    char* sm = smem_u;
    uint32_t ubase = s2u(sm);
    float* ls   = (float*)sm;                       // post-GEMM alias (34336B)
    float* red2 = (float*)(sm + S1STG);             // post-GEMM alias (8448B)
    float* bsm  = (float*)(sm + G1_BIAS);

    int tid = threadIdx.x, wid = tid >> 5, lane = tid & 31;
    int g = lane >> 2, t = lane & 3;
    int row0 = wid * 16;
    int n = blockIdx.x >> 3, blk = blockIdx.x & 7;
    int hw0 = blk << 7;

    // trans-A lane base: lanes 0-7: c rows kk+0..7 @hw row0; 8-15: +hw8; 16-23: c+8; 24-31: c+8,hw+8
    int atrow = ((lane & 7) + ((lane >> 4) << 3)) * 136 + row0 + (lane & 8);
    int brow  = ((lane & 7) + ((lane >> 4) << 3)) * 72 + (((lane >> 3) & 1) << 3);

    if (tid < K_) bsm[tid] = bias[tid];

    float acc[8][4];
    #pragma unroll
    for (int nb = 0; nb < 8; nb++)
        #pragma unroll
        for (int i = 0; i < 4; i++) acc[nb][i] = 0.f;

    auto issue = [&](int stage, int tile) {
        uint32_t sb = ubase + stage * S1STG;
        int cc = tile << 6;
        #pragma unroll
        for (int i = 0; i < 4; i++) {
            int idx = tid + (i << 8);
            int row = idx >> 4, q = idx & 15;
            size_t so = (size_t)(n * C_ + cc + row) * HW_ + hw0 + q * 8;
            cpa(sb + row * 272 + q * 16, g_xhi + so);
            cpa(sb + S1_AL + row * 272 + q * 16, g_xlo + so);
        }
        #pragma unroll
        for (int i = 0; i < 2; i++) {
            int idx = tid + (i << 8);
            int row = idx >> 3, q = idx & 7;
            int so = row * C_ + cc + q * 8;
            cpa(sb + S1_BH + row * 144 + q * 16, g_whi + so);
            cpa(sb + S1_BL + row * 144 + q * 16, g_wlo + so);
        }
    };

    issue(0, 0);
    CP_COMMIT();
    #pragma unroll 1
    for (int it = 0; it < 8; it++) {
        if (it < 7) { issue((it + 1) & 1, it + 1); CP_COMMIT(); CP_WAIT1(); }
        else        { CP_WAIT0(); }
        __syncthreads();
        uint32_t uAH = ubase + (it & 1) * S1STG;
        uint32_t uAL = uAH + S1_AL, uBH = uAH + S1_BH, uBL = uAH + S1_BL;
        #pragma unroll
        for (int kk = 0; kk < 64; kk += 16) {
            uint32_t ah0, ah1, ah2, ah3, al0, al1, al2, al3;
            ldsm_x4_t(ah0, ah1, ah2, ah3, uAH + (uint32_t)(atrow + kk * 136) * 2);
            ldsm_x4_t(al0, al1, al2, al3, uAL + (uint32_t)(atrow + kk * 136) * 2);
            #pragma unroll
            for (int nb2 = 0; nb2 < 4; nb2++) {
                uint32_t off = (uint32_t)(nb2 * 16 * 72 + brow + kk) * 2;
                uint32_t b0, b1, b2, b3;
                ldsm_x4(b0, b1, b2, b3, uBH + off);
                mma16816(acc[2 * nb2    ], ah0, ah1, ah2, ah3, b0, b1);
                mma16816(acc[2 * nb2 + 1], ah0, ah1, ah2, ah3, b2, b3);
                mma16816(acc[2 * nb2    ], al0, al1, al2, al3, b0, b1);
                mma16816(acc[2 * nb2 + 1], al0, al1, al2, al3, b2, b3);
                uint32_t c0, c1, c2, c3;
                ldsm_x4(c0, c1, c2, c3, uBL + off);
                mma16816(acc[2 * nb2    ], ah0, ah1, ah2, ah3, c0, c1);
                mma16816(acc[2 * nb2 + 1], ah0, ah1, ah2, ah3, c2, c3);
            }
        }
        __syncthreads();
    }

    #pragma unroll
    for (int nb = 0; nb < 8; nb++) {
        int col = nb * 8 + 2 * t;
        ls[(row0 + g    ) * 67 + col    ] = acc[nb][0];
        ls[(row0 + g    ) * 67 + col + 1] = acc[nb][1];
        ls[(row0 + g + 8) * 67 + col    ] = acc[nb][2];
        ls[(row0 + g + 8) * 67 + col + 1] = acc[nb][3];
    }
    __syncthreads();
    if (tid < 128) {
        int hw = hw0 + tid;
        float f[64];
        float m = -1e30f;
        float* sp = sa + (size_t)n * K_ * HW_ + hw;
        #pragma unroll
        for (int k = 0; k < K_; k++) {
            float raw = ls[tid * 67 + k];
            sp[(size_t)k * HW_] = raw;
            float v = (raw + bsm[k]) * ALPHA_;
            f[k] = v;
            m = fmaxf(m, v);
        }
        float s = 0.f;
        #pragma unroll
        for (int k = 0; k < K_; k++) { float e = __expf(f[k] - m); f[k] = e; s += e; }
        float is = 1.f / s;
        #pragma unroll
        for (int k = 0; k < K_; k++) ls[tid * 67 + k] = f[k] * is;
    }
    __syncthreads();
    {
        u16* ah = g_ahi + (size_t)n * K_ * HW_ + hw0;
        u16* al = g_alo + (size_t)n * K_ * HW_ + hw0;
        #pragma unroll
        for (int it2 = 0; it2 < 8; it2++) {
            int idx = tid + it2 * 256;
            int k = idx >> 5, q = idx & 31;
            float a0 = ls[(4 * q    ) * 67 + k];
            float a1 = ls[(4 * q + 1) * 67 + k];
            float a2 = ls[(4 * q + 2) * 67 + k];
            float a3 = ls[(4 * q + 3) * 67 + k];
            u16 h0, l0, h1, l1, h2, l2, h3, l3;
            split1(a0, h0, l0); split1(a1, h1, l1);
            split1(a2, h2, l2); split1(a3, h3, l3);
            uint2 hp = make_uint2((uint32_t)h0 | ((uint32_t)h1 << 16),
                                  (uint32_t)h2 | ((uint32_t)h3 << 16));
            uint2 lp = make_uint2((uint32_t)l0 | ((uint32_t)l1 << 16),
                                  (uint32_t)l2 | ((uint32_t)l3 << 16));
            *(uint2*)(ah + (size_t)k * HW_ + 4 * q) = hp;
            *(uint2*)(al + (size_t)k * HW_ + 4 * q) = lp;
            red2[k * 33 + q] = (a0 + a1) + (a2 + a3);
        }
    }
    __syncthreads();
    if (tid < K_) {
        float s = 0.f;
        #pragma unroll
        for (int q = 0; q < 32; q++) s += red2[tid * 33 + q];
        g_asum_part[(n * 8 + blk) * K_ + tid] = s;
    }
}

// ---------------------------------------------------------------------------
// kG2: D[128c][64k] = (x*inv) @ a^T, contraction h. Pure-copy staging from
// g_xhi/g_xlo [c][h] and g_ahi/g_alo [k][h]. cp.async double-buffered.
// stage: AH[128][72] 18432 | AL 18432 | BH[64][72] 9216 | BL 9216 = 55296
// ---------------------------------------------------------------------------
#define S2STG   55296
#define S2_AL   18432
#define S2_BH   36864
#define S2_BL   46080
#define G2_ASUM 110592
#define G2_SMEM 110848

__global__ void __launch_bounds__(256, 2)
kG2(const float* __restrict__ w, float* __restrict__ vlad) {
    char* sm = smem_u;
    uint32_t ubase = s2u(sm);
    float* ls   = (float*)sm;                       // post-GEMM alias
    float* asum = (float*)(sm + G2_ASUM);

    int tid = threadIdx.x, wid = tid >> 5, lane = tid & 31;
    int g = lane >> 2, t = lane & 3;
    int row0 = wid * 16;
    int n = blockIdx.x >> 2, ct = blockIdx.x & 3;
    int c0b = ct << 7;

    int arow = (row0 + (lane & 15)) * 72 + ((lane >> 4) << 3);
    int brow = ((lane & 7) + ((lane >> 4) << 3)) * 72 + (((lane >> 3) & 1) << 3);

    if (tid < K_) {
        const float* pp = g_asum_part + n * 8 * K_ + tid;
        float s = 0.f;
        #pragma unroll
        for (int b = 0; b < 8; b++) s += pp[b * K_];
        asum[tid] = s;
    }

    float acc[8][4];
    #pragma unroll
    for (int nb = 0; nb < 8; nb++)
        #pragma unroll
        for (int i = 0; i < 4; i++) acc[nb][i] = 0.f;

    auto issue = [&](int stage, int tile) {
        uint32_t sb = ubase + stage * S2STG;
        int h0 = tile << 6;
        #pragma unroll
        for (int i = 0; i < 4; i++) {
            int idx = tid + (i << 8);
            int row = idx >> 3, q = idx & 7;
            size_t so = (size_t)(n * C_ + c0b + row) * HW_ + h0 + q * 8;
            cpa(sb + row * 144 + q * 16, g_xhi + so);
            cpa(sb + S2_AL + row * 144 + q * 16, g_xlo + so);
        }
        #pragma unroll
        for (int i = 0; i < 2; i++) {
            int idx = tid + (i << 8);
            int row = idx >> 3, q = idx & 7;
            size_t so = (size_t)(n * K_ + row) * HW_ + h0 + q * 8;
            cpa(sb + S2_BH + row * 144 + q * 16, g_ahi + so);
            cpa(sb + S2_BL + row * 144 + q * 16, g_alo + so);
        }
    };

    issue(0, 0);
    CP_COMMIT();
    #pragma unroll 1
    for (int it = 0; it < 16; it++) {
        if (it < 15) { issue((it + 1) & 1, it + 1); CP_COMMIT(); CP_WAIT1(); }
        else         { CP_WAIT0(); }
        __syncthreads();
        uint32_t uAH = ubase + (it & 1) * S2STG;
        uint32_t uAL = uAH + S2_AL, uBH = uAH + S2_BH, uBL = uAH + S2_BL;
        #pragma unroll
        for (int kk = 0; kk < 64; kk += 16) {
            uint32_t ah0, ah1, ah2, ah3, al0, al1, al2, al3;
            ldsm_x4(ah0, ah1, ah2, ah3, uAH + (uint32_t)(arow + kk) * 2);
            ldsm_x4(al0, al1, al2, al3, uAL + (uint32_t)(arow + kk) * 2);
            #pragma unroll
            for (int nb2 = 0; nb2 < 4; nb2++) {
                uint32_t off = (uint32_t)(nb2 * 16 * 72 + brow + kk) * 2;
                uint32_t b0, b1, b2, b3;
                ldsm_x4(b0, b1, b2, b3, uBH + off);
                mma16816(acc[2 * nb2    ], ah0, ah1, ah2, ah3, b0, b1);
                mma16816(acc[2 * nb2 + 1], ah0, ah1, ah2, ah3, b2, b3);
                mma16816(acc[2 * nb2    ], al0, al1, al2, al3, b0, b1);
                mma16816(acc[2 * nb2 + 1], al0, al1, al2, al3, b2, b3);
                uint32_t c0, c1, c2, c3;
                ldsm_x4(c0, c1, c2, c3, uBL + off);
                mma16816(acc[2 * nb2    ], ah0, ah1, ah2, ah3, c0, c1);
                mma16816(acc[2 * nb2 + 1], ah0, ah1, ah2, ah3, c2, c3);
            }
        }
        __syncthreads();
    }

    #pragma unroll
    for (int nb = 0; nb < 8; nb++) {
        int col = nb * 8 + 2 * t;
        ls[(row0 + g    ) * 67 + col    ] = acc[nb][0];
        ls[(row0 + g    ) * 67 + col + 1] = acc[nb][1];
        ls[(row0 + g + 8) * 67 + col    ] = acc[nb][2];
        ls[(row0 + g + 8) * 67 + col + 1] = acc[nb][3];
    }
    __syncthreads();
    if (tid < 128) {
        int c = c0b + tid;
        float f[64];
        #pragma unroll
        for (int i = 0; i < 16; i++) {
            float4 wv = *(const float4*)(w + (size_t)c * K_ + 4 * i);
            f[4 * i    ] = ls[tid * 67 + 4 * i    ] - asum[4 * i    ] * wv.x;
            f[4 * i + 1] = ls[tid * 67 + 4 * i + 1] - asum[4 * i + 1] * wv.y;
            f[4 * i + 2] = ls[tid * 67 + 4 * i + 2] - asum[4 * i + 2] * wv.z;
            f[4 * i + 3] = ls[tid * 67 + 4 * i + 3] - asum[4 * i + 3] * wv.w;
        }
        float* vp = vlad + (size_t)n * K_ * C_ + c;
        #pragma unroll
        for (int k = 0; k < K_; k++) {
            vp[(size_t)k * C_] = f[k];
            ls[tid * 67 + k] = f[k];
        }
    }
    __syncthreads();
    if (tid < K_) {
        float s = 0.f;
        #pragma unroll 4
        for (int c = 0; c < 128; c++) { float v = ls[c * 67 + tid]; s += v * v; }
        g_ssq[(n * K_ + tid) * 4 + ct] = s;
    }
}

// ---------------------------------------------------------------------------
// k3: row L2 norm of vlad
// ---------------------------------------------------------------------------
__global__ void k3_kernel(float* __restrict__ vlad) {
    int row = blockIdx.x;
    const float* sp = g_ssq + row * 4;
    float ssq = (sp[0] + sp[1]) + (sp[2] + sp[3]);
    float iv = 1.f / fmaxf(sqrtf(ssq), EPS_);
    float4* vp = (float4*)(vlad + (size_t)row * C_);
    float4 v = vp[threadIdx.x];
    v.x *= iv; v.y *= iv; v.z *= iv; v.w *= iv;
    vp[threadIdx.x] = v;
}

// ---------------------------------------------------------------------------
extern "C" void kernel_launch(void* const* d_in, const int* in_sizes, int n_in,
                              void* d_out, int out_size) {
    const float* x    = (const float*)d_in[0];   // [64,512,32,32]
    const float* w    = (const float*)d_in[1];   // [512,64]
    const float* bias = (const float*)d_in[2];   // [64]
    float* out  = (float*)d_out;
    float* vlad = out;                                    // [64, 64*512]
    float* sa   = out + (size_t)N_ * K_ * C_;             // [64, 64, 1024]
    float* feat = sa  + (size_t)N_ * K_ * HW_;            // [64, 1024, 512]

    cudaFuncSetAttribute(kT2, cudaFuncAttributeMaxDynamicSharedMemorySize, T2_SMEM);
    cudaFuncSetAttribute(kG1, cudaFuncAttributeMaxDynamicSharedMemorySize, G1_SMEM);
    cudaFuncSetAttribute(kG2, cudaFuncAttributeMaxDynamicSharedMemorySize, G2_SMEM);

    k0_kernel<<<K_, 256>>>(w);
    kT2<<<N_ * 32, 256, T2_SMEM>>>(x, feat);
    kG1<<<N_ * 8, 256, G1_SMEM>>>(bias, sa);
    kG2<<<N_ * 4, 256, G2_SMEM>>>(w, vlad);
    k3_kernel<<<N_ * K_, 128>>>(vlad);
}